// round 11
// baseline (speedup 1.0000x reference)
#include <cuda_runtime.h>
#include <cuda_bf16.h>
#include <math.h>

#define NB 512
#define NT 64
#define NS 30
#define ND 200
#define NH 200
#define NA 12
#define NE 1024
#define OUTC 380
#define R 4
#define NCTA (NB / R)   // 128

typedef unsigned long long ull;

// ---------------- device-global scratch (allocation-free rule) ----------------
// k-pair-lane layouts: each 32-bit bf16 word = (w_k, w_{k+1}) for ONE column;
// uint2 = 4 k. fp32 float4 = 4 k. Padded in k4 for prefetch overrun (zero-init).
__device__ __align__(16) uint2  g_Wb [103 * 600];  // GRU bf16   [k4][600]
__device__ __align__(16) uint2  g_IOb[ 53 * 400];  // img|obs bf16 [k4][400]
__device__ __align__(16) float4 g_EFf[ 52 * 120];  // ims|obs fp32 [k4][120]
__device__ __align__(16) float4 g_INf[  8 * 200];  // inp fp32   [k4][200] (k 30,31 zero)
__device__ float g_pre_inp[NB * NT * NH];
__device__ float g_pre_obs[NB * NT * NH];

// ---------------- packed f32x2 helpers ----------------
__device__ __forceinline__ ull pack2(float lo, float hi) {
    ull r; asm("mov.b64 %0, {%1, %2};" : "=l"(r) : "f"(lo), "f"(hi)); return r;
}
__device__ __forceinline__ void unpack2(ull v, float& lo, float& hi) {
    asm("mov.b64 {%0, %1}, %2;" : "=f"(lo), "=f"(hi) : "l"(v));
}
__device__ __forceinline__ ull fma2(ull a, ull b, ull c) {
    ull d; asm("fma.rn.f32x2 %0, %1, %2, %3;" : "=l"(d) : "l"(a), "l"(b), "l"(c)); return d;
}
__device__ __forceinline__ ull add2(ull a, ull b) {
    ull d; asm("add.rn.f32x2 %0, %1, %2;" : "=l"(d) : "l"(a), "l"(b)); return d;
}
// bf16 pair -> f32x2: lo = p<<16, hi = p & 0xFFFF0000 (2 ALU, no CVT/MOV tax)
__device__ __forceinline__ ull bfpair(unsigned p) {
    unsigned lo = p << 16;
    unsigned hi = p & 0xFFFF0000u;
    ull r; asm("mov.b64 %0, {%1, %2};" : "=l"(r) : "r"(lo), "r"(hi));
    return r;
}
__device__ __forceinline__ unsigned pbf(float a, float b) {
    unsigned ua = (unsigned)__bfloat16_as_ushort(__float2bfloat16(a));
    unsigned ub = (unsigned)__bfloat16_as_ushort(__float2bfloat16(b));
    return ua | (ub << 16);
}

// ---------------- math helpers ----------------
__device__ __forceinline__ float eluf(float z)      { return z > 0.f ? z : expm1f(z); }
__device__ __forceinline__ float sigmoidf_(float z) { return 1.f / (1.f + expf(-z)); }
__device__ __forceinline__ float softplusf_(float z){ return fmaxf(z, 0.f) + log1pf(expf(-fabsf(z))); }

// =====================================================================
// Kernel 1: precompute + weight conversion (merged => 2 launches/call,
// so ncu capture index lands on the scan kernel)
// =====================================================================
#define PRE_ROWS 32
#define PRE_KC   256
#define PRE_PAD  36

__global__ void __launch_bounds__(224) precompute_kernel(
    const float* __restrict__ embed,
    const float* __restrict__ action,
    const float* __restrict__ obs_out_W,
    const float* __restrict__ obs_out_b,
    const float* __restrict__ inp_W,
    const float* __restrict__ inp_b,
    const float* __restrict__ gru_W,
    const float* __restrict__ img_W,
    const float* __restrict__ ims_W,
    const float* __restrict__ obs_W)
{
    // ---- weight conversion (grid-stride over flat ids) ----
    {
        int gt = blockIdx.x * blockDim.x + threadIdx.x;
        if (gt < 100 * 600) {          // GRU bf16 k-pairs
            int k4 = gt / 600, c = gt % 600, k = 4 * k4;
            g_Wb[k4 * 600 + c] = make_uint2(
                pbf(gru_W[k * 600 + c],       gru_W[(k + 1) * 600 + c]),
                pbf(gru_W[(k + 2) * 600 + c], gru_W[(k + 3) * 600 + c]));
        }
        if (gt < 50 * 400) {           // IO bf16 k-pairs
            int k4 = gt / 400, c = gt % 400, k = 4 * k4;
            const float* W = (c < 200) ? img_W : obs_out_W;
            int cc = (c < 200) ? c : c - 200;
            g_IOb[k4 * 400 + c] = make_uint2(
                pbf(W[k * 200 + cc],       W[(k + 1) * 200 + cc]),
                pbf(W[(k + 2) * 200 + cc], W[(k + 3) * 200 + cc]));
        }
        if (gt < 50 * 120) {           // EF fp32 k-quads
            int k4 = gt / 120, c = gt % 120, k = 4 * k4;
            const float* W = (c < 60) ? ims_W : obs_W;
            int cc = (c < 60) ? c : c - 60;
            g_EFf[k4 * 120 + c] = make_float4(
                W[k * 60 + cc], W[(k + 1) * 60 + cc],
                W[(k + 2) * 60 + cc], W[(k + 3) * 60 + cc]);
        }
        if (gt < 8 * 200) {            // IN fp32 k-quads (k 30,31 -> 0)
            int k4 = gt / 200, j = gt % 200, k = 4 * k4;
            float v[4];
#pragma unroll
            for (int e = 0; e < 4; e++) {
                int kk = k + e;
                v[e] = (kk < NS) ? inp_W[kk * 200 + j] : 0.f;
            }
            g_INf[k4 * 200 + j] = make_float4(v[0], v[1], v[2], v[3]);
        }
    }

    // ---- precompute pre_obs / pre_inp (unchanged math) ----
    __shared__ __align__(16) float s_aT[PRE_KC * PRE_PAD];
    __shared__ float s_act[PRE_ROWS * NA];

    const int bt0 = blockIdx.x * PRE_ROWS;
    const int tid = threadIdx.x;
    const int j   = tid;

    ull acc[16];
    {
        float b = (j < NH) ? obs_out_b[j] : 0.f;
        ull bb = pack2(b, b);
#pragma unroll
        for (int i = 0; i < 16; i++) acc[i] = bb;
    }

    const float* W2 = obs_out_W + (size_t)ND * NH;

    for (int kc = 0; kc < NE; kc += PRE_KC) {
        __syncthreads();
        for (int idx = tid; idx < PRE_ROWS * PRE_KC; idx += blockDim.x) {
            int rr = idx / PRE_KC;
            int kk = idx % PRE_KC;
            s_aT[kk * PRE_PAD + rr] = embed[(size_t)(bt0 + rr) * NE + kc + kk];
        }
        __syncthreads();

        if (j < NH) {
#pragma unroll 2
            for (int kk = 0; kk < PRE_KC; kk++) {
                float w = W2[(size_t)(kc + kk) * NH + j];
                ull wv = pack2(w, w);
                const ulonglong2* ap = (const ulonglong2*)&s_aT[kk * PRE_PAD];
#pragma unroll
                for (int q = 0; q < 8; q++) {
                    ulonglong2 a = ap[q];
                    acc[2 * q]     = fma2(a.x, wv, acc[2 * q]);
                    acc[2 * q + 1] = fma2(a.y, wv, acc[2 * q + 1]);
                }
            }
        }
    }

    if (j < NH) {
#pragma unroll
        for (int q = 0; q < 8; q++) {
            float v0, v1, v2, v3;
            unpack2(acc[2 * q],     v0, v1);
            unpack2(acc[2 * q + 1], v2, v3);
            g_pre_obs[(size_t)(bt0 + 4 * q + 0) * NH + j] = v0;
            g_pre_obs[(size_t)(bt0 + 4 * q + 1) * NH + j] = v1;
            g_pre_obs[(size_t)(bt0 + 4 * q + 2) * NH + j] = v2;
            g_pre_obs[(size_t)(bt0 + 4 * q + 3) * NH + j] = v3;
        }
    }

    __syncthreads();
    for (int idx = tid; idx < PRE_ROWS * NA; idx += blockDim.x) {
        int rr = idx / NA, kk = idx % NA;
        s_act[idx] = action[(size_t)(bt0 + rr) * NA + kk];
    }
    __syncthreads();

    if (j < NH) {
        float ib = inp_b[j];
        float wA[NA];
#pragma unroll
        for (int k = 0; k < NA; k++) wA[k] = inp_W[(NS + k) * NH + j];
        for (int rr = 0; rr < PRE_ROWS; rr++) {
            float a = ib;
#pragma unroll
            for (int k = 0; k < NA; k++) a = fmaf(s_act[rr * NA + k], wA[k], a);
            g_pre_inp[(size_t)(bt0 + rr) * NH + j] = a;
        }
    }
}

// =====================================================================
// Kernel 2: scan. 128 CTAs x 4 rows, 640 threads.
// k-pair-lane accumulation: fma2 lanes = adjacent k of SAME column.
// Activations stored transposed s_*T[r][k]; weights are ready pairs.
// =====================================================================
__global__ void __launch_bounds__(640) scan_kernel(
    const float* __restrict__ noise_prior,
    const float* __restrict__ noise_post,
    const float* __restrict__ gru_b,
    const float* __restrict__ img_out_b,
    const float* __restrict__ ims_b,
    const float* __restrict__ obs_b,
    float* __restrict__ out)
{
    __shared__ __align__(16) float s_xT[4 * 400];      // [r][k]: x (k<200) | deter
    __shared__ __align__(16) float s_stochT[4 * 32];   // [r][k] (k 30,31 zero)
    __shared__ __align__(16) float s_gates[600 * 4];   // [c][r] GRU gate pre-acts
    __shared__ __align__(16) float s_hT [4 * 200];     // [r][k]
    __shared__ __align__(16) float s_hoT[4 * 200];     // [r][k]
    __shared__ __align__(16) float s_pi [200 * 4];     // [j][r] staged pre_inp
    __shared__ __align__(16) float s_po2[200 * 4];     // [j][r] staged pre_obs
    __shared__ __align__(16) ull   s_efp[240 * 4];     // E/F partials

    const int tid  = threadIdx.x;
    const int row0 = blockIdx.x * R;

    for (int i = tid; i < 4 * 400; i += 640) s_xT[i] = 0.f;
    for (int i = tid; i < 4 * 32;  i += 640) s_stochT[i] = 0.f;
    for (int i = tid; i < 200 * 4; i += 640) {
        int j = i >> 2, r = i & 3;
        size_t base = ((size_t)(row0 + r) * NT + 0) * NH + j;
        s_pi [i] = g_pre_inp[base];
        s_po2[i] = g_pre_obs[base];
    }
    __syncthreads();

    for (int t = 0; t < NT; t++) {
        // ===== A: x = elu(stoch @ inp_W[:30] + pre_inp)  (200 threads) =====
        if (tid < 200) {
            const int j = tid;
            ull a0 = 0, a1 = 0, a2 = 0, a3 = 0;
            const float4* wp = g_INf + j;
#pragma unroll
            for (int i = 0; i < 8; i++) {
                float4 w = wp[i * 200];
                ull w01 = pack2(w.x, w.y), w23 = pack2(w.z, w.w);
                int k = 4 * i;
                ulonglong2 v0 = *(const ulonglong2*)&s_stochT[0 * 32 + k];
                ulonglong2 v1 = *(const ulonglong2*)&s_stochT[1 * 32 + k];
                ulonglong2 v2 = *(const ulonglong2*)&s_stochT[2 * 32 + k];
                ulonglong2 v3 = *(const ulonglong2*)&s_stochT[3 * 32 + k];
                a0 = fma2(v0.x, w01, a0); a0 = fma2(v0.y, w23, a0);
                a1 = fma2(v1.x, w01, a1); a1 = fma2(v1.y, w23, a1);
                a2 = fma2(v2.x, w01, a2); a2 = fma2(v2.y, w23, a2);
                a3 = fma2(v3.x, w01, a3); a3 = fma2(v3.y, w23, a3);
            }
            float lo, hi;
            unpack2(a0, lo, hi); s_xT[0 * 400 + j] = eluf(lo + hi + s_pi[j * 4 + 0]);
            unpack2(a1, lo, hi); s_xT[1 * 400 + j] = eluf(lo + hi + s_pi[j * 4 + 1]);
            unpack2(a2, lo, hi); s_xT[2 * 400 + j] = eluf(lo + hi + s_pi[j * 4 + 2]);
            unpack2(a3, lo, hi); s_xT[3 * 400 + j] = eluf(lo + hi + s_pi[j * 4 + 3]);
        }
        __syncthreads();

        // ===== B: GRU dots (600 threads; col=tid; K=400; bf16 k-pairs) =====
        if (tid < 600) {
            const int c = tid;
            ull a0 = 0, a1 = 0, a2 = 0, a3 = 0;
            const uint2* wp = g_Wb + c;
            uint2 w0 = wp[0], w1 = wp[600], w2 = wp[1200];
#pragma unroll 4
            for (int i = 0; i < 100; i++) {
                uint2 wn = wp[(size_t)(i + 3) * 600];
                ull w01 = bfpair(w0.x), w23 = bfpair(w0.y);
                const int k = 4 * i;
                ulonglong2 v0 = *(const ulonglong2*)&s_xT[0 * 400 + k];
                ulonglong2 v1 = *(const ulonglong2*)&s_xT[1 * 400 + k];
                ulonglong2 v2 = *(const ulonglong2*)&s_xT[2 * 400 + k];
                ulonglong2 v3 = *(const ulonglong2*)&s_xT[3 * 400 + k];
                a0 = fma2(v0.x, w01, a0); a0 = fma2(v0.y, w23, a0);
                a1 = fma2(v1.x, w01, a1); a1 = fma2(v1.y, w23, a1);
                a2 = fma2(v2.x, w01, a2); a2 = fma2(v2.y, w23, a2);
                a3 = fma2(v3.x, w01, a3); a3 = fma2(v3.y, w23, a3);
                w0 = w1; w1 = w2; w2 = wn;
            }
            float b = gru_b[c];
            float lo, hi, g0, g1, g2, g3;
            unpack2(a0, lo, hi); g0 = lo + hi + b;
            unpack2(a1, lo, hi); g1 = lo + hi + b;
            unpack2(a2, lo, hi); g2 = lo + hi + b;
            unpack2(a3, lo, hi); g3 = lo + hi + b;
            *(float4*)&s_gates[c * 4] = make_float4(g0, g1, g2, g3);
        }
        __syncthreads();

        // ===== B2: gate combine -> deter_new (200 threads) =====
        if (tid < 200) {
            const int u = tid;
            const float* gr = &s_gates[u * 4];
            const float* gc = &s_gates[(200 + u) * 4];
            const float* gu = &s_gates[(400 + u) * 4];
#pragma unroll
            for (int r = 0; r < R; r++) {
                float reset = sigmoidf_(gr[r]);
                float cand  = tanhf(reset * gc[r]);
                float upd   = sigmoidf_(gu[r] - 1.0f);
                float dold  = s_xT[r * 400 + 200 + u];
                float dn    = upd * cand + (1.f - upd) * dold;
                s_xT[r * 400 + 200 + u] = dn;
                out[(((size_t)(row0 + r)) * NT + t) * OUTC + 180 + u] = dn;
            }
        }
        __syncthreads();

        // ===== C/D: h / ho (400 threads; col = [img|obs]; K=200; bf16) =====
        if (tid < 400) {
            const int c = tid;
            ull a0 = 0, a1 = 0, a2 = 0, a3 = 0;
            const uint2* wp = g_IOb + c;
            uint2 w0 = wp[0], w1 = wp[400], w2 = wp[800];
#pragma unroll 4
            for (int i = 0; i < 50; i++) {
                uint2 wn = wp[(size_t)(i + 3) * 400];
                ull w01 = bfpair(w0.x), w23 = bfpair(w0.y);
                const int k = 200 + 4 * i;   // deter region of s_xT
                ulonglong2 v0 = *(const ulonglong2*)&s_xT[0 * 400 + k];
                ulonglong2 v1 = *(const ulonglong2*)&s_xT[1 * 400 + k];
                ulonglong2 v2 = *(const ulonglong2*)&s_xT[2 * 400 + k];
                ulonglong2 v3 = *(const ulonglong2*)&s_xT[3 * 400 + k];
                a0 = fma2(v0.x, w01, a0); a0 = fma2(v0.y, w23, a0);
                a1 = fma2(v1.x, w01, a1); a1 = fma2(v1.y, w23, a1);
                a2 = fma2(v2.x, w01, a2); a2 = fma2(v2.y, w23, a2);
                a3 = fma2(v3.x, w01, a3); a3 = fma2(v3.y, w23, a3);
                w0 = w1; w1 = w2; w2 = wn;
            }
            float lo, hi;
            if (c < 200) {
                float b = img_out_b[c];
                unpack2(a0, lo, hi); s_hT[0 * 200 + c] = eluf(lo + hi + b);
                unpack2(a1, lo, hi); s_hT[1 * 200 + c] = eluf(lo + hi + b);
                unpack2(a2, lo, hi); s_hT[2 * 200 + c] = eluf(lo + hi + b);
                unpack2(a3, lo, hi); s_hT[3 * 200 + c] = eluf(lo + hi + b);
            } else {
                const int j = c - 200;
                unpack2(a0, lo, hi); s_hoT[0 * 200 + j] = eluf(lo + hi + s_po2[j * 4 + 0]);
                unpack2(a1, lo, hi); s_hoT[1 * 200 + j] = eluf(lo + hi + s_po2[j * 4 + 1]);
                unpack2(a2, lo, hi); s_hoT[2 * 200 + j] = eluf(lo + hi + s_po2[j * 4 + 2]);
                unpack2(a3, lo, hi); s_hoT[3 * 200 + j] = eluf(lo + hi + s_po2[j * 4 + 3]);
            }
        }
        __syncthreads();

        // ===== E/F: stat layers x2 k-split (240 thr, fp32) + stage t+1 (160 thr) =====
        if (tid < 240) {
            const int q = tid / 120;     // k-half (100 k each)
            const int c = tid % 120;     // 0..59 ims, 60..119 obs
            const float* src = (c < 60) ? s_hT : s_hoT;
            ull a0 = 0, a1 = 0, a2 = 0, a3 = 0;
            const float4* wp = g_EFf + (size_t)(q * 25) * 120 + c;
            float4 w0 = wp[0], w1 = wp[120];
#pragma unroll 4
            for (int i = 0; i < 25; i++) {
                float4 wn = wp[(size_t)(i + 2) * 120];
                ull w01 = pack2(w0.x, w0.y), w23 = pack2(w0.z, w0.w);
                const int k = q * 100 + 4 * i;
                ulonglong2 v0 = *(const ulonglong2*)&src[0 * 200 + k];
                ulonglong2 v1 = *(const ulonglong2*)&src[1 * 200 + k];
                ulonglong2 v2 = *(const ulonglong2*)&src[2 * 200 + k];
                ulonglong2 v3 = *(const ulonglong2*)&src[3 * 200 + k];
                a0 = fma2(v0.x, w01, a0); a0 = fma2(v0.y, w23, a0);
                a1 = fma2(v1.x, w01, a1); a1 = fma2(v1.y, w23, a1);
                a2 = fma2(v2.x, w01, a2); a2 = fma2(v2.y, w23, a2);
                a3 = fma2(v3.x, w01, a3); a3 = fma2(v3.y, w23, a3);
                w0 = w1; w1 = wn;
            }
            ull* sp = &s_efp[tid * 4];
            sp[0] = a0; sp[1] = a1; sp[2] = a2; sp[3] = a3;
        } else if (tid >= 400 && tid < 560 && t + 1 < NT) {
            for (int i = tid - 400; i < 200 * 4; i += 160) {
                int j = i >> 2, r = i & 3;
                size_t base = ((size_t)(row0 + r) * NT + (t + 1)) * NH + j;
                s_pi [i] = g_pre_inp[base];
                s_po2[i] = g_pre_obs[base];
            }
        }
        __syncthreads();

        // ===== finalize: combine E/F partials, sample, write, carry =====
        if (tid < NS) {                       // prior (ims cols u, 30+u)
            const int u = tid;
            float mm[R], ss[R];
#pragma unroll
            for (int r = 0; r < R; r++) {
                ull am = add2(s_efp[u * 4 + r],        s_efp[(120 + u) * 4 + r]);
                ull as = add2(s_efp[(30 + u) * 4 + r], s_efp[(150 + u) * 4 + r]);
                float lo, hi;
                unpack2(am, lo, hi); mm[r] = lo + hi + ims_b[u];
                unpack2(as, lo, hi); ss[r] = lo + hi + ims_b[30 + u];
            }
#pragma unroll
            for (int r = 0; r < R; r++) {
                float sd = softplusf_(ss[r]) + 0.1f;
                size_t bt = ((size_t)(row0 + r)) * NT + t;
                float nz = noise_prior[bt * NS + u];
                size_t ob = bt * OUTC;
                out[ob + 120 + u] = mm[r];
                out[ob + 150 + u] = sd;
                out[ob +  90 + u] = mm[r] + sd * nz;
            }
        } else if (tid >= 32 && tid < 32 + NS) {  // posterior (obs cols 60+u, 90+u)
            const int u = tid - 32;
            float mm[R], ss[R];
#pragma unroll
            for (int r = 0; r < R; r++) {
                ull am = add2(s_efp[(60 + u) * 4 + r], s_efp[(180 + u) * 4 + r]);
                ull as = add2(s_efp[(90 + u) * 4 + r], s_efp[(210 + u) * 4 + r]);
                float lo, hi;
                unpack2(am, lo, hi); mm[r] = lo + hi + obs_b[u];
                unpack2(as, lo, hi); ss[r] = lo + hi + obs_b[30 + u];
            }
#pragma unroll
            for (int r = 0; r < R; r++) {
                float sd = softplusf_(ss[r]) + 0.1f;
                size_t bt = ((size_t)(row0 + r)) * NT + t;
                float nz = noise_post[bt * NS + u];
                float st = mm[r] + sd * nz;
                size_t ob = bt * OUTC;
                out[ob + 30 + u] = mm[r];
                out[ob + 60 + u] = sd;
                out[ob +  0 + u] = st;
                s_stochT[r * 32 + u] = st;   // transposed carry
            }
        }
        __syncthreads();
    }
}

// =====================================================================
extern "C" void kernel_launch(void* const* d_in, const int* in_sizes, int n_in,
                              void* d_out, int out_size) {
    const float* embed       = (const float*)d_in[0];
    const float* action      = (const float*)d_in[1];
    const float* noise_prior = (const float*)d_in[2];
    const float* noise_post  = (const float*)d_in[3];
    const float* inp_W       = (const float*)d_in[4];
    const float* inp_b       = (const float*)d_in[5];
    const float* gru_W       = (const float*)d_in[6];
    const float* gru_b       = (const float*)d_in[7];
    const float* img_out_W   = (const float*)d_in[8];
    const float* img_out_b   = (const float*)d_in[9];
    const float* ims_W       = (const float*)d_in[10];
    const float* ims_b       = (const float*)d_in[11];
    const float* obs_out_W   = (const float*)d_in[12];
    const float* obs_out_b   = (const float*)d_in[13];
    const float* obs_W       = (const float*)d_in[14];
    const float* obs_b       = (const float*)d_in[15];
    float* out = (float*)d_out;

    precompute_kernel<<<(NB * NT) / PRE_ROWS, 224>>>(embed, action, obs_out_W, obs_out_b,
                                                     inp_W, inp_b, gru_W, img_out_W,
                                                     ims_W, obs_W);
    scan_kernel<<<NCTA, 640>>>(noise_prior, noise_post, gru_b,
                               img_out_b, ims_b, obs_b, out);
}

// round 12
// speedup vs baseline: 1.0213x; 1.0213x over previous
#include <cuda_runtime.h>
#include <cuda_fp16.h>
#include <math.h>

#define NB 512
#define NT 64
#define NS 30
#define ND 200
#define NH 200
#define NA 12
#define NE 1024
#define OUTC 380
#define NCTA 128        // 4 rows per CTA = 2 groups x 2 rows

typedef unsigned long long ull;

// ---------------- device-global scratch (allocation-free rule) ----------------
// fp16 k-quad weights: uint2 = 4 halves = W[4k4..4k4+3][c]; padded in k4.
__device__ __align__(16) uint2  g_Whq [102 * 600];  // GRU
__device__ __align__(16) uint2  g_IOhq[ 52 * 400];  // [img(200)|obs_out(200)]
__device__ __align__(16) float4 g_EFq [ 52 * 120];  // [ims(60)|obs(60)] fp32 k-quads
__device__ __align__(16) float4 g_INf [  8 * 200];  // inp fp32 k-quads (k>=30 zero)
__device__ float g_pre_inp[NB * NT * NH];
__device__ float g_pre_obs[NB * NT * NH];

// ---------------- packed f32x2 helpers ----------------
__device__ __forceinline__ ull pack2(float lo, float hi) {
    ull r; asm("mov.b64 %0, {%1, %2};" : "=l"(r) : "f"(lo), "f"(hi)); return r;
}
__device__ __forceinline__ void unpack2(ull v, float& lo, float& hi) {
    asm("mov.b64 {%0, %1}, %2;" : "=f"(lo), "=f"(hi) : "l"(v));
}
__device__ __forceinline__ ull fma2(ull a, ull b, ull c) {
    ull d; asm("fma.rn.f32x2 %0, %1, %2, %3;" : "=l"(d) : "l"(a), "l"(b), "l"(c)); return d;
}
__device__ __forceinline__ ull add2(ull a, ull b) {
    ull d; asm("add.rn.f32x2 %0, %1, %2;" : "=l"(d) : "l"(a), "l"(b)); return d;
}

#define GBAR(g) asm volatile("bar.sync %0, 320;" :: "r"((g) + 1) : "memory")

// ---------------- math helpers ----------------
__device__ __forceinline__ float eluf(float z)      { return z > 0.f ? z : expm1f(z); }
__device__ __forceinline__ float sigmoidf_(float z) { return 1.f / (1.f + expf(-z)); }
__device__ __forceinline__ float softplusf_(float z){ return fmaxf(z, 0.f) + log1pf(expf(-fabsf(z))); }

// =====================================================================
// Kernel 1: precompute + weight conversion (merged: 2 launches/call)
// =====================================================================
#define PRE_ROWS 32
#define PRE_KC   256
#define PRE_PAD  36

__global__ void __launch_bounds__(224) precompute_kernel(
    const float* __restrict__ embed,
    const float* __restrict__ action,
    const float* __restrict__ obs_out_W,
    const float* __restrict__ obs_out_b,
    const float* __restrict__ inp_W,
    const float* __restrict__ inp_b,
    const float* __restrict__ gru_W,
    const float* __restrict__ img_W,
    const float* __restrict__ ims_W,
    const float* __restrict__ obs_W)
{
    // ---- weight conversion ----
    {
        int gt = blockIdx.x * blockDim.x + threadIdx.x;
        if (gt < 102 * 600) {
            int k4 = gt / 600, c = gt % 600, k = 4 * k4;
            float v0 = (k     < 400) ? gru_W[(k)     * 600 + c] : 0.f;
            float v1 = (k + 1 < 400) ? gru_W[(k + 1) * 600 + c] : 0.f;
            float v2 = (k + 2 < 400) ? gru_W[(k + 2) * 600 + c] : 0.f;
            float v3 = (k + 3 < 400) ? gru_W[(k + 3) * 600 + c] : 0.f;
            __half2 h01 = __floats2half2_rn(v0, v1);
            __half2 h23 = __floats2half2_rn(v2, v3);
            g_Whq[gt] = make_uint2(*(unsigned*)&h01, *(unsigned*)&h23);
        }
        if (gt < 52 * 400) {
            int k4 = gt / 400, c = gt % 400, k = 4 * k4;
            const float* W = (c < 200) ? img_W : obs_out_W;
            int cc = (c < 200) ? c : c - 200;
            float v[4];
#pragma unroll
            for (int e = 0; e < 4; e++) {
                int kk = k + e;
                v[e] = (kk < 200) ? W[kk * 200 + cc] : 0.f;
            }
            __half2 h01 = __floats2half2_rn(v[0], v[1]);
            __half2 h23 = __floats2half2_rn(v[2], v[3]);
            g_IOhq[gt] = make_uint2(*(unsigned*)&h01, *(unsigned*)&h23);
        }
        if (gt < 52 * 120) {
            int k4 = gt / 120, c = gt % 120, k = 4 * k4;
            const float* W = (c < 60) ? ims_W : obs_W;
            int cc = (c < 60) ? c : c - 60;
            float v[4];
#pragma unroll
            for (int e = 0; e < 4; e++) {
                int kk = k + e;
                v[e] = (kk < 200) ? W[kk * 60 + cc] : 0.f;
            }
            g_EFq[gt] = make_float4(v[0], v[1], v[2], v[3]);
        }
        if (gt < 8 * 200) {
            int k4 = gt / 200, j = gt % 200, k = 4 * k4;
            float v[4];
#pragma unroll
            for (int e = 0; e < 4; e++) {
                int kk = k + e;
                v[e] = (kk < NS) ? inp_W[kk * 200 + j] : 0.f;
            }
            g_INf[gt] = make_float4(v[0], v[1], v[2], v[3]);
        }
    }

    // ---- precompute pre_obs / pre_inp ----
    __shared__ __align__(16) float s_aT[PRE_KC * PRE_PAD];
    __shared__ float s_act[PRE_ROWS * NA];

    const int bt0 = blockIdx.x * PRE_ROWS;
    const int tid = threadIdx.x;
    const int j   = tid;

    ull acc[16];
    {
        float b = (j < NH) ? obs_out_b[j] : 0.f;
        ull bb = pack2(b, b);
#pragma unroll
        for (int i = 0; i < 16; i++) acc[i] = bb;
    }

    const float* W2 = obs_out_W + (size_t)ND * NH;

    for (int kc = 0; kc < NE; kc += PRE_KC) {
        __syncthreads();
        for (int idx = tid; idx < PRE_ROWS * PRE_KC; idx += blockDim.x) {
            int rr = idx / PRE_KC;
            int kk = idx % PRE_KC;
            s_aT[kk * PRE_PAD + rr] = embed[(size_t)(bt0 + rr) * NE + kc + kk];
        }
        __syncthreads();

        if (j < NH) {
#pragma unroll 2
            for (int kk = 0; kk < PRE_KC; kk++) {
                float w = W2[(size_t)(kc + kk) * NH + j];
                ull wv = pack2(w, w);
                const ulonglong2* ap = (const ulonglong2*)&s_aT[kk * PRE_PAD];
#pragma unroll
                for (int q = 0; q < 8; q++) {
                    ulonglong2 a = ap[q];
                    acc[2 * q]     = fma2(a.x, wv, acc[2 * q]);
                    acc[2 * q + 1] = fma2(a.y, wv, acc[2 * q + 1]);
                }
            }
        }
    }

    if (j < NH) {
#pragma unroll
        for (int q = 0; q < 8; q++) {
            float v0, v1, v2, v3;
            unpack2(acc[2 * q],     v0, v1);
            unpack2(acc[2 * q + 1], v2, v3);
            g_pre_obs[(size_t)(bt0 + 4 * q + 0) * NH + j] = v0;
            g_pre_obs[(size_t)(bt0 + 4 * q + 1) * NH + j] = v1;
            g_pre_obs[(size_t)(bt0 + 4 * q + 2) * NH + j] = v2;
            g_pre_obs[(size_t)(bt0 + 4 * q + 3) * NH + j] = v3;
        }
    }

    __syncthreads();
    for (int idx = tid; idx < PRE_ROWS * NA; idx += blockDim.x) {
        int rr = idx / NA, kk = idx % NA;
        s_act[idx] = action[(size_t)(bt0 + rr) * NA + kk];
    }
    __syncthreads();

    if (j < NH) {
        float ib = inp_b[j];
        float wA[NA];
#pragma unroll
        for (int k = 0; k < NA; k++) wA[k] = inp_W[(NS + k) * NH + j];
        for (int rr = 0; rr < PRE_ROWS; rr++) {
            float a = ib;
#pragma unroll
            for (int k = 0; k < NA; k++) a = fmaf(s_act[rr * NA + k], wA[k], a);
            g_pre_inp[(size_t)(bt0 + rr) * NH + j] = a;
        }
    }
}

// =====================================================================
// Kernel 2: scan. 128 CTAs, 640 threads = 2 INDEPENDENT groups x 320
// threads x 2 rows, named-barrier sync per group (groups desynchronize
// -> cross-phase latency hiding). fp16 k-quad weights, fp32 accum.
// Activations stored as (row0,row1) f32x2 words.
// =====================================================================
__global__ void __launch_bounds__(640) scan_kernel(
    const float* __restrict__ noise_prior,
    const float* __restrict__ noise_post,
    const float* __restrict__ gru_b,
    const float* __restrict__ img_out_b,
    const float* __restrict__ ims_b,
    const float* __restrict__ obs_b,
    float* __restrict__ out)
{
    __shared__ __align__(16) ull s_xd[2][400];    // [g][k]: x | deter, lanes = rows
    __shared__ __align__(16) ull s_g [2][600];    // GRU gate pre-acts
    __shared__ __align__(16) ull s_h [2][200];
    __shared__ __align__(16) ull s_ho[2][200];
    __shared__ __align__(16) ull s_pi[2][200];
    __shared__ __align__(16) ull s_po[2][200];
    __shared__ __align__(16) ull s_stoch[2][32];
    __shared__ __align__(16) ull s_efp[2][240];

    const int tid = threadIdx.x;
    const int g   = tid / 320;
    const int lt  = tid - g * 320;
    const int row0 = blockIdx.x * 4 + g * 2;   // group's first global row

    // prologue (full CTA)
    for (int i = tid; i < 2 * 400; i += 640) s_xd[i / 400][i % 400] = 0ull;
    for (int i = tid; i < 2 * 32;  i += 640) s_stoch[i / 32][i % 32] = 0ull;
    for (int i = tid; i < 2 * 2 * 200; i += 640) {
        int gg = i / 400, rem = i % 400, arr = rem / 200, j = rem % 200;
        int r0 = blockIdx.x * 4 + gg * 2;
        const float* src = arr ? g_pre_obs : g_pre_inp;
        ull* dst = arr ? s_po[gg] : s_pi[gg];
        float v0 = src[((size_t)r0 * NT + 0) * NH + j];
        float v1 = src[((size_t)(r0 + 1) * NT + 0) * NH + j];
        dst[j] = pack2(v0, v1);
    }
    __syncthreads();

    for (int t = 0; t < NT; t++) {
        // ===== A: x = elu(stoch @ inp_W[:30] + pre_inp)  (200 thr) =====
        if (lt < 200) {
            const int j = lt;
            ull a0 = s_pi[g][j], a1 = 0;
            const float4* wq = g_INf + j;
            const ull* sp = s_stoch[g];
#pragma unroll
            for (int i = 0; i < 8; i++) {
                float4 w = wq[i * 200];
                int k = 4 * i;
                a0 = fma2(sp[k],     pack2(w.x, w.x), a0);
                a1 = fma2(sp[k + 1], pack2(w.y, w.y), a1);
                a0 = fma2(sp[k + 2], pack2(w.z, w.z), a0);
                a1 = fma2(sp[k + 3], pack2(w.w, w.w), a1);
            }
            a0 = add2(a0, a1);
            float lo, hi;
            unpack2(a0, lo, hi);
            s_xd[g][j] = pack2(eluf(lo), eluf(hi));
        }
        GBAR(g);

        // ===== B: GRU dots (300 thr x 2 cols; K=400 fp16 quads) =====
        if (lt < 300) {
            const int c0 = lt, c1 = lt + 300;
            float bb0 = gru_b[c0], bb1 = gru_b[c1];
            ull a0 = pack2(bb0, bb0), b0 = 0;
            ull a1 = pack2(bb1, bb1), b1 = 0;
            const uint2* wp0 = g_Whq + c0;
            const uint2* wp1 = g_Whq + c1;
            const ull* ap = s_xd[g];
            uint2 w00 = wp0[0], w01 = wp0[600];
            uint2 w10 = wp1[0], w11 = wp1[600];
            for (int q = 0; q < 100; q++) {
                uint2 n0 = wp0[(size_t)(q + 2) * 600];
                uint2 n1 = wp1[(size_t)(q + 2) * 600];
                const int k = 4 * q;
                ull v0 = ap[k], v1 = ap[k + 1], v2 = ap[k + 2], v3 = ap[k + 3];
                float2 f01 = __half22float2(*(const __half2*)&w00.x);
                float2 f23 = __half22float2(*(const __half2*)&w00.y);
                a0 = fma2(v0, pack2(f01.x, f01.x), a0);
                b0 = fma2(v1, pack2(f01.y, f01.y), b0);
                a0 = fma2(v2, pack2(f23.x, f23.x), a0);
                b0 = fma2(v3, pack2(f23.y, f23.y), b0);
                f01 = __half22float2(*(const __half2*)&w10.x);
                f23 = __half22float2(*(const __half2*)&w10.y);
                a1 = fma2(v0, pack2(f01.x, f01.x), a1);
                b1 = fma2(v1, pack2(f01.y, f01.y), b1);
                a1 = fma2(v2, pack2(f23.x, f23.x), a1);
                b1 = fma2(v3, pack2(f23.y, f23.y), b1);
                w00 = w01; w01 = n0;
                w10 = w11; w11 = n1;
            }
            s_g[g][c0] = add2(a0, b0);
            s_g[g][c1] = add2(a1, b1);
        }
        GBAR(g);

        // ===== B2: gate combine -> deter_new (200 thr) =====
        if (lt < 200) {
            const int u = lt;
            float r0_, r1_, c0_, c1_, u0_, u1_, d0_, d1_;
            unpack2(s_g[g][u],       r0_, r1_);
            unpack2(s_g[g][200 + u], c0_, c1_);
            unpack2(s_g[g][400 + u], u0_, u1_);
            unpack2(s_xd[g][200 + u], d0_, d1_);
            float re0 = sigmoidf_(r0_), re1 = sigmoidf_(r1_);
            float ca0 = tanhf(re0 * c0_), ca1 = tanhf(re1 * c1_);
            float up0 = sigmoidf_(u0_ - 1.f), up1 = sigmoidf_(u1_ - 1.f);
            float dn0 = up0 * ca0 + (1.f - up0) * d0_;
            float dn1 = up1 * ca1 + (1.f - up1) * d1_;
            s_xd[g][200 + u] = pack2(dn0, dn1);
            out[(((size_t)row0)     * NT + t) * OUTC + 180 + u] = dn0;
            out[(((size_t)row0 + 1) * NT + t) * OUTC + 180 + u] = dn1;
        }
        GBAR(g);

        // ===== C/D: h & ho (200 thr x 2 cols [img c | obs c]; K=200) =====
        if (lt < 200) {
            const int c = lt;
            float ib = img_out_b[c];
            ull a0 = pack2(ib, ib), b0 = 0;
            ull a1 = s_po[g][c],    b1 = 0;
            const uint2* wp0 = g_IOhq + c;
            const uint2* wp1 = g_IOhq + 200 + c;
            const ull* ap = s_xd[g] + 200;
            uint2 w00 = wp0[0], w01 = wp0[400];
            uint2 w10 = wp1[0], w11 = wp1[400];
            for (int q = 0; q < 50; q++) {
                uint2 n0 = wp0[(size_t)(q + 2) * 400];
                uint2 n1 = wp1[(size_t)(q + 2) * 400];
                const int k = 4 * q;
                ull v0 = ap[k], v1 = ap[k + 1], v2 = ap[k + 2], v3 = ap[k + 3];
                float2 f01 = __half22float2(*(const __half2*)&w00.x);
                float2 f23 = __half22float2(*(const __half2*)&w00.y);
                a0 = fma2(v0, pack2(f01.x, f01.x), a0);
                b0 = fma2(v1, pack2(f01.y, f01.y), b0);
                a0 = fma2(v2, pack2(f23.x, f23.x), a0);
                b0 = fma2(v3, pack2(f23.y, f23.y), b0);
                f01 = __half22float2(*(const __half2*)&w10.x);
                f23 = __half22float2(*(const __half2*)&w10.y);
                a1 = fma2(v0, pack2(f01.x, f01.x), a1);
                b1 = fma2(v1, pack2(f01.y, f01.y), b1);
                a1 = fma2(v2, pack2(f23.x, f23.x), a1);
                b1 = fma2(v3, pack2(f23.y, f23.y), b1);
                w00 = w01; w01 = n0;
                w10 = w11; w11 = n1;
            }
            a0 = add2(a0, b0);
            a1 = add2(a1, b1);
            float lo, hi;
            unpack2(a0, lo, hi); s_h[g][c]  = pack2(eluf(lo), eluf(hi));
            unpack2(a1, lo, hi); s_ho[g][c] = pack2(eluf(lo), eluf(hi));
        }
        GBAR(g);

        // ===== E/F: stat layers x2 k-split (240 thr) + stage t+1 (80 thr) =====
        if (lt < 240) {
            const int q = lt / 120;     // k-half
            const int c = lt % 120;     // 0..59 ims, 60..119 obs
            const ull* src = ((c < 60) ? s_h[g] : s_ho[g]) + q * 100;
            ull a0 = 0, b0 = 0;
            const float4* wp = g_EFq + (size_t)(q * 25) * 120 + c;
            float4 w0 = wp[0], w1 = wp[120];
            for (int i = 0; i < 25; i++) {
                float4 wn = wp[(size_t)(i + 2) * 120];
                const int k = 4 * i;
                a0 = fma2(src[k],     pack2(w0.x, w0.x), a0);
                b0 = fma2(src[k + 1], pack2(w0.y, w0.y), b0);
                a0 = fma2(src[k + 2], pack2(w0.z, w0.z), a0);
                b0 = fma2(src[k + 3], pack2(w0.w, w0.w), b0);
                w0 = w1; w1 = wn;
            }
            s_efp[g][lt] = add2(a0, b0);
        } else if (lt >= 240 && t + 1 < NT) {
            for (int i = lt - 240; i < 400; i += 80) {
                int arr = i / 200, j = i % 200;
                const float* src = arr ? g_pre_obs : g_pre_inp;
                ull* dst = arr ? s_po[g] : s_pi[g];
                float v0 = src[((size_t)row0 * NT + (t + 1)) * NH + j];
                float v1 = src[((size_t)(row0 + 1) * NT + (t + 1)) * NH + j];
                dst[j] = pack2(v0, v1);
            }
        }
        GBAR(g);

        // ===== finalize: combine partials, sample, write, carry =====
        if (lt < NS) {                       // prior (ims cols u, 30+u)
            const int u = lt;
            ull am = add2(s_efp[g][u],      s_efp[g][120 + u]);
            ull as = add2(s_efp[g][30 + u], s_efp[g][150 + u]);
            float m0, m1, sp0, sp1;
            unpack2(am, m0, m1);
            unpack2(as, sp0, sp1);
            float bm = ims_b[u], bs = ims_b[30 + u];
            m0 += bm; m1 += bm;
            float sd0 = softplusf_(sp0 + bs) + 0.1f;
            float sd1 = softplusf_(sp1 + bs) + 0.1f;
            size_t bt0_ = ((size_t)row0) * NT + t;
            size_t bt1_ = ((size_t)row0 + 1) * NT + t;
            float nz0 = noise_prior[bt0_ * NS + u];
            float nz1 = noise_prior[bt1_ * NS + u];
            size_t ob0 = bt0_ * OUTC, ob1 = bt1_ * OUTC;
            out[ob0 + 120 + u] = m0;  out[ob1 + 120 + u] = m1;
            out[ob0 + 150 + u] = sd0; out[ob1 + 150 + u] = sd1;
            out[ob0 +  90 + u] = m0 + sd0 * nz0;
            out[ob1 +  90 + u] = m1 + sd1 * nz1;
        } else if (lt >= 32 && lt < 32 + NS) {   // posterior (obs cols 60+u, 90+u)
            const int u = lt - 32;
            ull am = add2(s_efp[g][60 + u], s_efp[g][180 + u]);
            ull as = add2(s_efp[g][90 + u], s_efp[g][210 + u]);
            float m0, m1, sp0, sp1;
            unpack2(am, m0, m1);
            unpack2(as, sp0, sp1);
            float bm = obs_b[u], bs = obs_b[30 + u];
            m0 += bm; m1 += bm;
            float sd0 = softplusf_(sp0 + bs) + 0.1f;
            float sd1 = softplusf_(sp1 + bs) + 0.1f;
            size_t bt0_ = ((size_t)row0) * NT + t;
            size_t bt1_ = ((size_t)row0 + 1) * NT + t;
            float nz0 = noise_post[bt0_ * NS + u];
            float nz1 = noise_post[bt1_ * NS + u];
            float st0 = m0 + sd0 * nz0;
            float st1 = m1 + sd1 * nz1;
            size_t ob0 = bt0_ * OUTC, ob1 = bt1_ * OUTC;
            out[ob0 + 30 + u] = m0;  out[ob1 + 30 + u] = m1;
            out[ob0 + 60 + u] = sd0; out[ob1 + 60 + u] = sd1;
            out[ob0 +  0 + u] = st0; out[ob1 +  0 + u] = st1;
            s_stoch[g][u] = pack2(st0, st1);
        }
        GBAR(g);
    }
}

// =====================================================================
extern "C" void kernel_launch(void* const* d_in, const int* in_sizes, int n_in,
                              void* d_out, int out_size) {
    const float* embed       = (const float*)d_in[0];
    const float* action      = (const float*)d_in[1];
    const float* noise_prior = (const float*)d_in[2];
    const float* noise_post  = (const float*)d_in[3];
    const float* inp_W       = (const float*)d_in[4];
    const float* inp_b       = (const float*)d_in[5];
    const float* gru_W       = (const float*)d_in[6];
    const float* gru_b       = (const float*)d_in[7];
    const float* img_out_W   = (const float*)d_in[8];
    const float* img_out_b   = (const float*)d_in[9];
    const float* ims_W       = (const float*)d_in[10];
    const float* ims_b       = (const float*)d_in[11];
    const float* obs_out_W   = (const float*)d_in[12];
    const float* obs_out_b   = (const float*)d_in[13];
    const float* obs_W       = (const float*)d_in[14];
    const float* obs_b       = (const float*)d_in[15];
    float* out = (float*)d_out;

    precompute_kernel<<<(NB * NT) / PRE_ROWS, 224>>>(embed, action, obs_out_W, obs_out_b,
                                                     inp_W, inp_b, gru_W, img_out_W,
                                                     ims_W, obs_W);
    scan_kernel<<<NCTA, 640>>>(noise_prior, noise_post, gru_b,
                               img_out_b, ims_b, obs_b, out);
}

// round 13
// speedup vs baseline: 1.1085x; 1.0854x over previous
#include <cuda_runtime.h>
#include <cuda_fp16.h>
#include <math.h>

#define NB 512
#define NT 64
#define NS 30
#define ND 200
#define NH 200
#define NA 12
#define NE 1024
#define OUTC 380
#define R 4
#define NCTA (NB / R)   // 128

typedef unsigned long long ull;

// ---------------- device-global scratch (allocation-free rule) ----------------
// fp16 k-quad weights: uint2 (8B) = 4 halves = W[4k4..4k4+3][c]; padded in k4
// (zeros) so the depth-4 prefetch ring may overrun.
__device__ __align__(16) uint2  g_Whq [108 * 600];  // GRU
__device__ __align__(16) uint2  g_IOhq[ 56 * 400];  // [img(200)|obs_out(200)]
__device__ __align__(16) float2 g_EFp [104 * 120];  // [ims(60)|obs(60)] fp32 k-pairs
__device__ float g_pre_inp[NB * NT * NH];
__device__ float g_pre_obs[NB * NT * NH];

// ---------------- packed f32x2 helpers ----------------
__device__ __forceinline__ ull pack2(float lo, float hi) {
    ull r; asm("mov.b64 %0, {%1, %2};" : "=l"(r) : "f"(lo), "f"(hi)); return r;
}
__device__ __forceinline__ void unpack2(ull v, float& lo, float& hi) {
    asm("mov.b64 {%0, %1}, %2;" : "=f"(lo), "=f"(hi) : "l"(v));
}
__device__ __forceinline__ ull fma2(ull a, ull b, ull c) {
    ull d; asm("fma.rn.f32x2 %0, %1, %2, %3;" : "=l"(d) : "l"(a), "l"(b), "l"(c)); return d;
}
__device__ __forceinline__ ull add2(ull a, ull b) {
    ull d; asm("add.rn.f32x2 %0, %1, %2;" : "=l"(d) : "l"(a), "l"(b)); return d;
}

// ---------------- math helpers ----------------
__device__ __forceinline__ float eluf(float z)      { return z > 0.f ? z : expm1f(z); }
__device__ __forceinline__ float sigmoidf_(float z) { return 1.f / (1.f + expf(-z)); }
__device__ __forceinline__ float softplusf_(float z){ return fmaxf(z, 0.f) + log1pf(expf(-fabsf(z))); }

// =====================================================================
// Kernel 1: precompute + weight conversion (merged: 2 launches/call so
// ncu -s 5 lands on the scan kernel)
// =====================================================================
#define PRE_ROWS 32
#define PRE_KC   256
#define PRE_PAD  36

__global__ void __launch_bounds__(224) precompute_kernel(
    const float* __restrict__ embed,
    const float* __restrict__ action,
    const float* __restrict__ obs_out_W,
    const float* __restrict__ obs_out_b,
    const float* __restrict__ inp_W,
    const float* __restrict__ inp_b,
    const float* __restrict__ gru_W,
    const float* __restrict__ img_W,
    const float* __restrict__ ims_W,
    const float* __restrict__ obs_W)
{
    // ---- weight conversion ----
    {
        int gt = blockIdx.x * blockDim.x + threadIdx.x;
        if (gt < 108 * 600) {
            int k4 = gt / 600, c = gt % 600, k = 4 * k4;
            float v0 = (k     < 400) ? gru_W[(k)     * 600 + c] : 0.f;
            float v1 = (k + 1 < 400) ? gru_W[(k + 1) * 600 + c] : 0.f;
            float v2 = (k + 2 < 400) ? gru_W[(k + 2) * 600 + c] : 0.f;
            float v3 = (k + 3 < 400) ? gru_W[(k + 3) * 600 + c] : 0.f;
            __half2 h01 = __floats2half2_rn(v0, v1);
            __half2 h23 = __floats2half2_rn(v2, v3);
            g_Whq[gt] = make_uint2(*(unsigned*)&h01, *(unsigned*)&h23);
        }
        if (gt < 56 * 400) {
            int k4 = gt / 400, c = gt % 400, k = 4 * k4;
            const float* W = (c < 200) ? img_W : obs_out_W;
            int cc = (c < 200) ? c : c - 200;
            float v[4];
#pragma unroll
            for (int e = 0; e < 4; e++) {
                int kk = k + e;
                v[e] = (kk < 200) ? W[kk * 200 + cc] : 0.f;
            }
            __half2 h01 = __floats2half2_rn(v[0], v[1]);
            __half2 h23 = __floats2half2_rn(v[2], v[3]);
            g_IOhq[gt] = make_uint2(*(unsigned*)&h01, *(unsigned*)&h23);
        }
        if (gt < 104 * 120) {
            int k2 = gt / 120, c = gt % 120;
            float lo = 0.f, hi = 0.f;
            int k0 = 2 * k2, k1 = 2 * k2 + 1;
            if (k0 < 200) lo = (c < 60) ? ims_W[k0 * 60 + c] : obs_W[k0 * 60 + c - 60];
            if (k1 < 200) hi = (c < 60) ? ims_W[k1 * 60 + c] : obs_W[k1 * 60 + c - 60];
            g_EFp[gt] = make_float2(lo, hi);
        }
    }

    // ---- precompute pre_obs / pre_inp (unchanged math) ----
    __shared__ __align__(16) float s_aT[PRE_KC * PRE_PAD];
    __shared__ float s_act[PRE_ROWS * NA];

    const int bt0 = blockIdx.x * PRE_ROWS;
    const int tid = threadIdx.x;
    const int j   = tid;

    ull acc[16];
    {
        float b = (j < NH) ? obs_out_b[j] : 0.f;
        ull bb = pack2(b, b);
#pragma unroll
        for (int i = 0; i < 16; i++) acc[i] = bb;
    }

    const float* W2 = obs_out_W + (size_t)ND * NH;

    for (int kc = 0; kc < NE; kc += PRE_KC) {
        __syncthreads();
        for (int idx = tid; idx < PRE_ROWS * PRE_KC; idx += blockDim.x) {
            int rr = idx / PRE_KC;
            int kk = idx % PRE_KC;
            s_aT[kk * PRE_PAD + rr] = embed[(size_t)(bt0 + rr) * NE + kc + kk];
        }
        __syncthreads();

        if (j < NH) {
#pragma unroll 2
            for (int kk = 0; kk < PRE_KC; kk++) {
                float w = W2[(size_t)(kc + kk) * NH + j];
                ull wv = pack2(w, w);
                const ulonglong2* ap = (const ulonglong2*)&s_aT[kk * PRE_PAD];
#pragma unroll
                for (int q = 0; q < 8; q++) {
                    ulonglong2 a = ap[q];
                    acc[2 * q]     = fma2(a.x, wv, acc[2 * q]);
                    acc[2 * q + 1] = fma2(a.y, wv, acc[2 * q + 1]);
                }
            }
        }
    }

    if (j < NH) {
#pragma unroll
        for (int q = 0; q < 8; q++) {
            float v0, v1, v2, v3;
            unpack2(acc[2 * q],     v0, v1);
            unpack2(acc[2 * q + 1], v2, v3);
            g_pre_obs[(size_t)(bt0 + 4 * q + 0) * NH + j] = v0;
            g_pre_obs[(size_t)(bt0 + 4 * q + 1) * NH + j] = v1;
            g_pre_obs[(size_t)(bt0 + 4 * q + 2) * NH + j] = v2;
            g_pre_obs[(size_t)(bt0 + 4 * q + 3) * NH + j] = v3;
        }
    }

    __syncthreads();
    for (int idx = tid; idx < PRE_ROWS * NA; idx += blockDim.x) {
        int rr = idx / NA, kk = idx % NA;
        s_act[idx] = action[(size_t)(bt0 + rr) * NA + kk];
    }
    __syncthreads();

    if (j < NH) {
        float ib = inp_b[j];
        float wA[NA];
#pragma unroll
        for (int k = 0; k < NA; k++) wA[k] = inp_W[(NS + k) * NH + j];
        for (int rr = 0; rr < PRE_ROWS; rr++) {
            float a = ib;
#pragma unroll
            for (int k = 0; k < NA; k++) a = fmaf(s_act[rr * NA + k], wA[k], a);
            g_pre_inp[(size_t)(bt0 + rr) * NH + j] = a;
        }
    }
}

// =====================================================================
// Kernel 2: scan. 128 CTAs x 4 rows, 640 threads.
// fp16 k-quad weights, fp32 accumulate, DEPTH-4 prefetch ring,
// 4 accumulator chains, E/F x4 split, pre-staging pipeline.
// =====================================================================
__global__ void __launch_bounds__(640) scan_kernel(
    const float* __restrict__ noise_prior,
    const float* __restrict__ noise_post,
    const float* __restrict__ inp_W,
    const float* __restrict__ gru_b,
    const float* __restrict__ img_out_b,
    const float* __restrict__ ims_b,
    const float* __restrict__ obs_b,
    float* __restrict__ out)
{
    __shared__ __align__(16) float s_xd[400 * R];   // x (0..199), deter (200..399)
    __shared__ __align__(16) float s_dn[200 * R];
    __shared__ __align__(16) float s_gr[200 * R];
    __shared__ __align__(16) float s_h [200 * R];
    __shared__ __align__(16) float s_ho[200 * R];
    __shared__ __align__(16) float s_pi [200 * R];
    __shared__ __align__(16) float s_po2[200 * R];
    __shared__ __align__(16) float s_stoch[32 * R];
    __shared__ __align__(16) ull   s_efp[480 * 2];

    const int tid  = threadIdx.x;
    const int row0 = blockIdx.x * R;

    for (int i = tid; i < 400 * R; i += 640) s_xd[i] = 0.f;
    for (int i = tid; i < 32 * R;  i += 640) s_stoch[i] = 0.f;
    for (int i = tid; i < 200 * R; i += 640) {
        int r = i / 200, j = i % 200;
        size_t base = ((size_t)(row0 + r) * NT + 0) * NH + j;
        s_pi [j * R + r] = g_pre_inp[base];
        s_po2[j * R + r] = g_pre_obs[base];
    }
    __syncthreads();

    for (int t = 0; t < NT; t++) {
        // ===== A: x = elu(stoch @ inp_W[:30] + pre_inp)  (200 threads) =====
        if (tid < 200) {
            const int j = tid;
            ull a0 = *(const ull*)&s_pi[j * R];
            ull a1 = *(const ull*)&s_pi[j * R + 2];
            const ulonglong2* ap = (const ulonglong2*)s_stoch;
#pragma unroll
            for (int k = 0; k < NS; k++) {
                float w = inp_W[k * NH + j];
                ull wv = pack2(w, w);
                ulonglong2 v = ap[k];
                a0 = fma2(v.x, wv, a0);
                a1 = fma2(v.y, wv, a1);
            }
            float lo, hi;
            unpack2(a0, lo, hi); s_xd[j*R+0]=eluf(lo); s_xd[j*R+1]=eluf(hi);
            unpack2(a1, lo, hi); s_xd[j*R+2]=eluf(lo); s_xd[j*R+3]=eluf(hi);
        }
        __syncthreads();

        // ===== B: GRU dots (600 threads; col=tid; 100 fp16 quads; depth-4 ring) =====
        if (tid < 600) {
            float b = gru_b[tid];
            ull a0 = pack2(b, b), a1 = a0;
            ull b0 = 0, b1 = 0, c0 = 0, c1 = 0, d0 = 0, d1 = 0;
            const uint2* wp = g_Whq + tid;
            const ulonglong2* ap = (const ulonglong2*)s_xd;
            uint2 w0 = wp[0], w1 = wp[600], w2 = wp[1200], w3 = wp[1800];
            for (int q = 0; q < 100; q += 2) {
                uint2 n0 = wp[(size_t)(q + 4) * 600];
                uint2 n1 = wp[(size_t)(q + 5) * 600];
                float2 f01 = __half22float2(*(const __half2*)&w0.x);
                float2 f23 = __half22float2(*(const __half2*)&w0.y);
                ulonglong2 v; ull wv;
                v = ap[4*q+0]; wv = pack2(f01.x, f01.x); a0 = fma2(v.x, wv, a0); a1 = fma2(v.y, wv, a1);
                v = ap[4*q+1]; wv = pack2(f01.y, f01.y); b0 = fma2(v.x, wv, b0); b1 = fma2(v.y, wv, b1);
                v = ap[4*q+2]; wv = pack2(f23.x, f23.x); c0 = fma2(v.x, wv, c0); c1 = fma2(v.y, wv, c1);
                v = ap[4*q+3]; wv = pack2(f23.y, f23.y); d0 = fma2(v.x, wv, d0); d1 = fma2(v.y, wv, d1);
                f01 = __half22float2(*(const __half2*)&w1.x);
                f23 = __half22float2(*(const __half2*)&w1.y);
                v = ap[4*q+4]; wv = pack2(f01.x, f01.x); a0 = fma2(v.x, wv, a0); a1 = fma2(v.y, wv, a1);
                v = ap[4*q+5]; wv = pack2(f01.y, f01.y); b0 = fma2(v.x, wv, b0); b1 = fma2(v.y, wv, b1);
                v = ap[4*q+6]; wv = pack2(f23.x, f23.x); c0 = fma2(v.x, wv, c0); c1 = fma2(v.y, wv, c1);
                v = ap[4*q+7]; wv = pack2(f23.y, f23.y); d0 = fma2(v.x, wv, d0); d1 = fma2(v.y, wv, d1);
                w0 = w2; w1 = w3; w2 = n0; w3 = n1;
            }
            a0 = add2(add2(a0, b0), add2(c0, d0));
            a1 = add2(add2(a1, b1), add2(c1, d1));
            const int g = tid / 200, u = tid % 200;
            float* gbuf = (g == 0) ? s_gr : (g == 1) ? s_h : s_ho;
            float lo, hi;
            unpack2(a0, lo, hi); gbuf[u*R+0]=lo; gbuf[u*R+1]=hi;
            unpack2(a1, lo, hi); gbuf[u*R+2]=lo; gbuf[u*R+3]=hi;
        }
        __syncthreads();

        // ===== B2: gate combine -> deter_new (200 threads) =====
        if (tid < 200) {
            const int u = tid;
#pragma unroll
            for (int r = 0; r < R; r++) {
                float reset = sigmoidf_(s_gr[u * R + r]);
                float cand  = tanhf(reset * s_h[u * R + r]);
                float upd   = sigmoidf_(s_ho[u * R + r] - 1.0f);
                float dold  = s_xd[(200 + u) * R + r];
                float dn    = upd * cand + (1.f - upd) * dold;
                s_dn[u * R + r] = dn;
                s_xd[(200 + u) * R + r] = dn;
                out[(((size_t)(row0 + r)) * NT + t) * OUTC + 180 + u] = dn;
            }
        }
        __syncthreads();

        // ===== C/D: h / ho (400 threads; 50 fp16 quads; depth-4 ring) =====
        if (tid < 400) {
            const int m = tid / 200;
            const int j = tid % 200;
            ull a0, a1;
            if (m == 0) {
                float b = img_out_b[j];
                a0 = pack2(b, b); a1 = a0;
            } else {
                a0 = *(const ull*)&s_po2[j * R];
                a1 = *(const ull*)&s_po2[j * R + 2];
            }
            ull b0 = 0, b1 = 0, c0 = 0, c1 = 0, d0 = 0, d1 = 0;
            const uint2* wp = g_IOhq + tid;
            const ulonglong2* ap = (const ulonglong2*)s_dn;
            uint2 w0 = wp[0], w1 = wp[400], w2 = wp[800], w3 = wp[1200];
            for (int q = 0; q < 50; q += 2) {
                uint2 n0 = wp[(size_t)(q + 4) * 400];
                uint2 n1 = wp[(size_t)(q + 5) * 400];
                float2 f01 = __half22float2(*(const __half2*)&w0.x);
                float2 f23 = __half22float2(*(const __half2*)&w0.y);
                ulonglong2 v; ull wv;
                v = ap[4*q+0]; wv = pack2(f01.x, f01.x); a0 = fma2(v.x, wv, a0); a1 = fma2(v.y, wv, a1);
                v = ap[4*q+1]; wv = pack2(f01.y, f01.y); b0 = fma2(v.x, wv, b0); b1 = fma2(v.y, wv, b1);
                v = ap[4*q+2]; wv = pack2(f23.x, f23.x); c0 = fma2(v.x, wv, c0); c1 = fma2(v.y, wv, c1);
                v = ap[4*q+3]; wv = pack2(f23.y, f23.y); d0 = fma2(v.x, wv, d0); d1 = fma2(v.y, wv, d1);
                f01 = __half22float2(*(const __half2*)&w1.x);
                f23 = __half22float2(*(const __half2*)&w1.y);
                v = ap[4*q+4]; wv = pack2(f01.x, f01.x); a0 = fma2(v.x, wv, a0); a1 = fma2(v.y, wv, a1);
                v = ap[4*q+5]; wv = pack2(f01.y, f01.y); b0 = fma2(v.x, wv, b0); b1 = fma2(v.y, wv, b1);
                v = ap[4*q+6]; wv = pack2(f23.x, f23.x); c0 = fma2(v.x, wv, c0); c1 = fma2(v.y, wv, c1);
                v = ap[4*q+7]; wv = pack2(f23.y, f23.y); d0 = fma2(v.x, wv, d0); d1 = fma2(v.y, wv, d1);
                w0 = w2; w1 = w3; w2 = n0; w3 = n1;
            }
            a0 = add2(add2(a0, b0), add2(c0, d0));
            a1 = add2(add2(a1, b1), add2(c1, d1));
            float* dst = (m == 0) ? s_h : s_ho;
            float lo, hi;
            unpack2(a0, lo, hi); dst[j*R+0]=eluf(lo); dst[j*R+1]=eluf(hi);
            unpack2(a1, lo, hi); dst[j*R+2]=eluf(lo); dst[j*R+3]=eluf(hi);
        }
        __syncthreads();

        // ===== E/F: stat layers x4 split (480 thr) + stage t+1 pre (160 thr) =====
        if (tid < 480) {
            const int q = tid / 120;
            const int c = tid % 120;
            const int m = c / 60;
            ull a0 = 0, a1 = 0;
            if (q == 0) {
                float b = (m == 0) ? ims_b[c] : obs_b[c - 60];
                a0 = pack2(b, b); a1 = a0;
            }
            const float2* wp = g_EFp + (q * 25) * 120 + c;
            const ulonglong2* ap = (const ulonglong2*)((m == 0) ? s_h : s_ho) + q * 50;
#pragma unroll
            for (int i = 0; i < 25; i++) {
                float2 w = wp[(size_t)i * 120];
                ull w0 = pack2(w.x, w.x), w1 = pack2(w.y, w.y);
                ulonglong2 vA = ap[2 * i], vB = ap[2 * i + 1];
                a0 = fma2(vA.x, w0, a0);  a1 = fma2(vA.y, w0, a1);
                a0 = fma2(vB.x, w1, a0);  a1 = fma2(vB.y, w1, a1);
            }
            s_efp[tid * 2]     = a0;
            s_efp[tid * 2 + 1] = a1;
        } else if (t + 1 < NT) {
            for (int i = tid - 480; i < 200 * R; i += 160) {
                int r = i / 200, j = i % 200;
                size_t base = ((size_t)(row0 + r) * NT + (t + 1)) * NH + j;
                s_pi [j * R + r] = g_pre_inp[base];
                s_po2[j * R + r] = g_pre_obs[base];
            }
        }
        __syncthreads();

        // ===== finalize: combine E/F partials, sample, write, carry =====
        if (tid < NS) {
            const int u = tid;
            ull m0 = 0, m1 = 0, s0 = 0, s1 = 0;
#pragma unroll
            for (int q = 0; q < 4; q++) {
                m0 = add2(m0, s_efp[(q * 120 + u) * 2]);
                m1 = add2(m1, s_efp[(q * 120 + u) * 2 + 1]);
                s0 = add2(s0, s_efp[(q * 120 + 30 + u) * 2]);
                s1 = add2(s1, s_efp[(q * 120 + 30 + u) * 2 + 1]);
            }
            float mm[R], ss[R];
            unpack2(m0, mm[0], mm[1]); unpack2(m1, mm[2], mm[3]);
            unpack2(s0, ss[0], ss[1]); unpack2(s1, ss[2], ss[3]);
#pragma unroll
            for (int r = 0; r < R; r++) {
                float sd = softplusf_(ss[r]) + 0.1f;
                size_t bt = ((size_t)(row0 + r)) * NT + t;
                float nz = noise_prior[bt * NS + u];
                size_t ob = bt * OUTC;
                out[ob + 120 + u] = mm[r];
                out[ob + 150 + u] = sd;
                out[ob +  90 + u] = mm[r] + sd * nz;
            }
        } else if (tid >= 32 && tid < 32 + NS) {
            const int u = tid - 32;
            ull m0 = 0, m1 = 0, s0 = 0, s1 = 0;
#pragma unroll
            for (int q = 0; q < 4; q++) {
                m0 = add2(m0, s_efp[(q * 120 + 60 + u) * 2]);
                m1 = add2(m1, s_efp[(q * 120 + 60 + u) * 2 + 1]);
                s0 = add2(s0, s_efp[(q * 120 + 90 + u) * 2]);
                s1 = add2(s1, s_efp[(q * 120 + 90 + u) * 2 + 1]);
            }
            float mm[R], ss[R];
            unpack2(m0, mm[0], mm[1]); unpack2(m1, mm[2], mm[3]);
            unpack2(s0, ss[0], ss[1]); unpack2(s1, ss[2], ss[3]);
#pragma unroll
            for (int r = 0; r < R; r++) {
                float sd = softplusf_(ss[r]) + 0.1f;
                size_t bt = ((size_t)(row0 + r)) * NT + t;
                float nz = noise_post[bt * NS + u];
                float st = mm[r] + sd * nz;
                size_t ob = bt * OUTC;
                out[ob + 30 + u] = mm[r];
                out[ob + 60 + u] = sd;
                out[ob +  0 + u] = st;
                s_stoch[u * R + r] = st;
            }
        }
        __syncthreads();
    }
}

// =====================================================================
extern "C" void kernel_launch(void* const* d_in, const int* in_sizes, int n_in,
                              void* d_out, int out_size) {
    const float* embed       = (const float*)d_in[0];
    const float* action      = (const float*)d_in[1];
    const float* noise_prior = (const float*)d_in[2];
    const float* noise_post  = (const float*)d_in[3];
    const float* inp_W       = (const float*)d_in[4];
    const float* inp_b       = (const float*)d_in[5];
    const float* gru_W       = (const float*)d_in[6];
    const float* gru_b       = (const float*)d_in[7];
    const float* img_out_W   = (const float*)d_in[8];
    const float* img_out_b   = (const float*)d_in[9];
    const float* ims_W       = (const float*)d_in[10];
    const float* ims_b       = (const float*)d_in[11];
    const float* obs_out_W   = (const float*)d_in[12];
    const float* obs_out_b   = (const float*)d_in[13];
    const float* obs_W       = (const float*)d_in[14];
    const float* obs_b       = (const float*)d_in[15];
    float* out = (float*)d_out;

    precompute_kernel<<<(NB * NT) / PRE_ROWS, 224>>>(embed, action, obs_out_W, obs_out_b,
                                                     inp_W, inp_b, gru_W, img_out_W,
                                                     ims_W, obs_W);
    scan_kernel<<<NCTA, 640>>>(noise_prior, noise_post, inp_W, gru_b,
                               img_out_b, ims_b, obs_b, out);
}

// round 14
// speedup vs baseline: 1.4424x; 1.3012x over previous
#include <cuda_runtime.h>
#include <cuda_fp16.h>
#include <math.h>

#define NB 512
#define NT 64
#define NS 30
#define ND 200
#define NH 200
#define NA 12
#define NE 1024
#define OUTC 380
#define R 4
#define NCTA (NB / R)   // 128

// MMA tilings (m16n8k16)
#define KS_GRU 26       // K = 416 (400 + bias row + pad)
#define NTI_GRU 76      // N = 608 (600 + pad)
#define KS_IO  14       // K = 224-ish (200 deter + bias + pad)
#define NTI_IO 50       // N = 400 (img 200 | obs 200)
#define KS_EF  14
#define NTI_EF 16       // E: 8 tiles (64 cols), F: 8 tiles

// ---------------- device-global scratch (allocation-free rule) ----------------
// Weights pre-packed in HMMA B-fragment lane order: one uint2 per (tile,ks,lane).
__device__ __align__(16) uint2 g_WB_gru[NTI_GRU * KS_GRU * 32];
__device__ __align__(16) uint2 g_WB_io [NTI_IO  * KS_IO  * 32];
__device__ __align__(16) uint2 g_WB_ef [NTI_EF  * KS_EF  * 32];
__device__ float g_pre_inp[NB * NT * NH];
__device__ float g_pre_obs[NB * NT * NH];

typedef unsigned long long ull;

// ---------------- helpers ----------------
__device__ __forceinline__ unsigned h2(float a, float b) {
    __half2 h = __floats2half2_rn(a, b);
    return *(unsigned*)&h;
}
__device__ __forceinline__ ull pack2(float lo, float hi) {
    ull r; asm("mov.b64 %0, {%1, %2};" : "=l"(r) : "f"(lo), "f"(hi)); return r;
}
__device__ __forceinline__ void unpack2(ull v, float& lo, float& hi) {
    asm("mov.b64 {%0, %1}, %2;" : "=f"(lo), "=f"(hi) : "l"(v));
}
__device__ __forceinline__ ull fma2(ull a, ull b, ull c) {
    ull d; asm("fma.rn.f32x2 %0, %1, %2, %3;" : "=l"(d) : "l"(a), "l"(b), "l"(c)); return d;
}
__device__ __forceinline__ void mma16816(float& c0, float& c1, float& c2, float& c3,
                                         unsigned a0, unsigned a1, unsigned a2, unsigned a3,
                                         unsigned b0, unsigned b1) {
    asm volatile(
        "mma.sync.aligned.m16n8k16.row.col.f32.f16.f16.f32 "
        "{%0,%1,%2,%3},{%4,%5,%6,%7},{%8,%9},{%0,%1,%2,%3};"
        : "+f"(c0), "+f"(c1), "+f"(c2), "+f"(c3)
        : "r"(a0), "r"(a1), "r"(a2), "r"(a3), "r"(b0), "r"(b1));
}
__device__ __forceinline__ float eluf(float z)      { return z > 0.f ? z : expm1f(z); }
__device__ __forceinline__ float sigmoidf_(float z) { return 1.f / (1.f + expf(-z)); }
__device__ __forceinline__ float softplusf_(float z){ return fmaxf(z, 0.f) + log1pf(expf(-fabsf(z))); }

// =====================================================================
// Kernel 1: precompute + MMA-fragment weight packing (2 launches/call)
// =====================================================================
#define PRE_ROWS 32
#define PRE_KC   256
#define PRE_PAD  36

__global__ void __launch_bounds__(224) precompute_kernel(
    const float* __restrict__ embed,
    const float* __restrict__ action,
    const float* __restrict__ obs_out_W,
    const float* __restrict__ obs_out_b,
    const float* __restrict__ inp_W,
    const float* __restrict__ inp_b,
    const float* __restrict__ gru_W,
    const float* __restrict__ gru_b,
    const float* __restrict__ img_W,
    const float* __restrict__ img_out_b,
    const float* __restrict__ ims_W,
    const float* __restrict__ ims_b,
    const float* __restrict__ obs_W,
    const float* __restrict__ obs_b)
{
    // ---- pack weights into HMMA B-fragments ----
    {
        int gt = blockIdx.x * blockDim.x + threadIdx.x;
        // GRU: K rows = [x(200); deter(200); bias(=gru_b); zeros]
        if (gt < NTI_GRU * KS_GRU * 32) {
            int lane = gt & 31;
            int ks   = (gt >> 5) % KS_GRU;
            int tile = (gt >> 5) / KS_GRU;
            int tk = lane & 3, gc = lane >> 2;
            int n = tile * 8 + gc;
            int k0 = ks * 16 + 2 * tk;
            float v[4];
#pragma unroll
            for (int e = 0; e < 4; e++) {
                int k = k0 + (e >= 2 ? 8 : 0) + (e & 1);
                float w = 0.f;
                if (n < 600) {
                    if (k < 400) w = gru_W[k * 600 + n];
                    else if (k == 400) w = gru_b[n];
                }
                v[e] = w;
            }
            g_WB_gru[gt] = make_uint2(h2(v[0], v[1]), h2(v[2], v[3]));
        }
        // IO: K rows = [deter(200); bias(img only); zeros]; tiles 0-24 img, 25-49 obs
        if (gt < NTI_IO * KS_IO * 32) {
            int lane = gt & 31;
            int ks   = (gt >> 5) % KS_IO;
            int tile = (gt >> 5) / KS_IO;
            int tk = lane & 3, gc = lane >> 2;
            bool is_img = tile < 25;
            int n = (is_img ? tile : tile - 25) * 8 + gc;   // < 200
            int k0 = ks * 16 + 2 * tk;
            float v[4];
#pragma unroll
            for (int e = 0; e < 4; e++) {
                int k = k0 + (e >= 2 ? 8 : 0) + (e & 1);
                float w = 0.f;
                if (k < 200) w = (is_img ? img_W : obs_out_W)[k * 200 + n];
                else if (k == 200 && is_img) w = img_out_b[n];
                v[e] = w;
            }
            g_WB_io[gt] = make_uint2(h2(v[0], v[1]), h2(v[2], v[3]));
        }
        // EF: K rows = [h/ho(200); bias; zeros]; tiles 0-7 ims(E), 8-15 obs(F)
        if (gt < NTI_EF * KS_EF * 32) {
            int lane = gt & 31;
            int ks   = (gt >> 5) % KS_EF;
            int tile = (gt >> 5) / KS_EF;
            int tk = lane & 3, gc = lane >> 2;
            bool is_e = tile < 8;
            int n = (is_e ? tile : tile - 8) * 8 + gc;      // < 64
            int k0 = ks * 16 + 2 * tk;
            float v[4];
#pragma unroll
            for (int e = 0; e < 4; e++) {
                int k = k0 + (e >= 2 ? 8 : 0) + (e & 1);
                float w = 0.f;
                if (n < 60) {
                    if (k < 200) w = (is_e ? ims_W : obs_W)[k * 60 + n];
                    else if (k == 200) w = (is_e ? ims_b : obs_b)[n];
                }
                v[e] = w;
            }
            g_WB_ef[gt] = make_uint2(h2(v[0], v[1]), h2(v[2], v[3]));
        }
    }

    // ---- precompute pre_obs / pre_inp (fp32, unchanged) ----
    __shared__ __align__(16) float s_aT[PRE_KC * PRE_PAD];
    __shared__ float s_act[PRE_ROWS * NA];

    const int bt0 = blockIdx.x * PRE_ROWS;
    const int tid = threadIdx.x;
    const int j   = tid;

    ull acc[16];
    {
        float b = (j < NH) ? obs_out_b[j] : 0.f;
        ull bb = pack2(b, b);
#pragma unroll
        for (int i = 0; i < 16; i++) acc[i] = bb;
    }

    const float* W2 = obs_out_W + (size_t)ND * NH;

    for (int kc = 0; kc < NE; kc += PRE_KC) {
        __syncthreads();
        for (int idx = tid; idx < PRE_ROWS * PRE_KC; idx += blockDim.x) {
            int rr = idx / PRE_KC;
            int kk = idx % PRE_KC;
            s_aT[kk * PRE_PAD + rr] = embed[(size_t)(bt0 + rr) * NE + kc + kk];
        }
        __syncthreads();

        if (j < NH) {
#pragma unroll 2
            for (int kk = 0; kk < PRE_KC; kk++) {
                float w = W2[(size_t)(kc + kk) * NH + j];
                ull wv = pack2(w, w);
                const ulonglong2* ap = (const ulonglong2*)&s_aT[kk * PRE_PAD];
#pragma unroll
                for (int q = 0; q < 8; q++) {
                    ulonglong2 a = ap[q];
                    acc[2 * q]     = fma2(a.x, wv, acc[2 * q]);
                    acc[2 * q + 1] = fma2(a.y, wv, acc[2 * q + 1]);
                }
            }
        }
    }

    if (j < NH) {
#pragma unroll
        for (int q = 0; q < 8; q++) {
            float v0, v1, v2, v3;
            unpack2(acc[2 * q],     v0, v1);
            unpack2(acc[2 * q + 1], v2, v3);
            g_pre_obs[(size_t)(bt0 + 4 * q + 0) * NH + j] = v0;
            g_pre_obs[(size_t)(bt0 + 4 * q + 1) * NH + j] = v1;
            g_pre_obs[(size_t)(bt0 + 4 * q + 2) * NH + j] = v2;
            g_pre_obs[(size_t)(bt0 + 4 * q + 3) * NH + j] = v3;
        }
    }

    __syncthreads();
    for (int idx = tid; idx < PRE_ROWS * NA; idx += blockDim.x) {
        int rr = idx / NA, kk = idx % NA;
        s_act[idx] = action[(size_t)(bt0 + rr) * NA + kk];
    }
    __syncthreads();

    if (j < NH) {
        float ib = inp_b[j];
        float wA[NA];
#pragma unroll
        for (int k = 0; k < NA; k++) wA[k] = inp_W[(NS + k) * NH + j];
        for (int rr = 0; rr < PRE_ROWS; rr++) {
            float a = ib;
#pragma unroll
            for (int k = 0; k < NA; k++) a = fmaf(s_act[rr * NA + k], wA[k], a);
            g_pre_inp[(size_t)(bt0 + rr) * NH + j] = a;
        }
    }
}

// =====================================================================
// Kernel 2: scan via warp-level HMMA. 128 CTAs x 4 rows, 640 threads.
// Activations as fp16 (k,k+1)-pair A-fragments in smem; fp32 recurrent
// master state; biases folded as K-rows.
// =====================================================================
__global__ void __launch_bounds__(640) scan_kernel(
    const float* __restrict__ noise_prior,
    const float* __restrict__ noise_post,
    const float* __restrict__ inp_W,
    float* __restrict__ out)
{
    __shared__ __align__(16) unsigned s_xA [4 * 216];  // [r][pair]: x(0-99) deter(100-199) bias@200
    __shared__ __align__(16) unsigned s_hA [4 * 116];  // h pairs 0-99, bias@100
    __shared__ __align__(16) unsigned s_hoA[4 * 116];
    __shared__ __align__(16) float s_gates[4 * 608];
    __shared__ __align__(16) float s_det  [4 * 200];   // fp32 master deter
    __shared__ __align__(16) float s_stat [4 * 128];   // E: 0-63, F: 64-127
    __shared__ __align__(16) float s_pi [800];         // [j][r]
    __shared__ __align__(16) float s_po2[800];
    __shared__ __align__(16) float s_stoch[128];       // [r][k]

    const int tid  = threadIdx.x;
    const int wid  = tid >> 5;
    const int lane = tid & 31;
    const int tk   = lane & 3;
    const int gr   = lane >> 2;
    const int row0 = blockIdx.x * R;

    for (int i = tid; i < 4 * 216; i += 640) { int p = i % 216; s_xA[i] = (p == 200) ? 0x00003C00u : 0u; }
    for (int i = tid; i < 4 * 116; i += 640) { int p = i % 116; unsigned v = (p == 100) ? 0x00003C00u : 0u; s_hA[i] = v; s_hoA[i] = v; }
    for (int i = tid; i < 800; i += 640) s_det[i] = 0.f;
    for (int i = tid; i < 128; i += 640) s_stoch[i] = 0.f;
    for (int i = tid; i < 800; i += 640) {
        int j = i >> 2, r = i & 3;
        size_t base = ((size_t)(row0 + r) * NT + 0) * NH + j;
        s_pi [i] = g_pre_inp[base];
        s_po2[i] = g_pre_obs[base];
    }
    __syncthreads();

    for (int t = 0; t < NT; t++) {
        // ===== A: x = elu(stoch @ inp_W[:30] + pre_inp) (200 thr, fp32) =====
        if (tid < 200) {
            const int j = tid;
            float4 acc = *(const float4*)&s_pi[j * 4];
#pragma unroll
            for (int k = 0; k < NS; k++) {
                float w = inp_W[k * NH + j];
                acc.x = fmaf(w, s_stoch[0 * 32 + k], acc.x);
                acc.y = fmaf(w, s_stoch[1 * 32 + k], acc.y);
                acc.z = fmaf(w, s_stoch[2 * 32 + k], acc.z);
                acc.w = fmaf(w, s_stoch[3 * 32 + k], acc.w);
            }
            __half* xh = (__half*)s_xA;
            int half_idx = (j >> 1) * 2 + (j & 1);
            xh[(0 * 216) * 2 + half_idx] = __float2half(eluf(acc.x));
            xh[(1 * 216) * 2 + half_idx] = __float2half(eluf(acc.y));
            xh[(2 * 216) * 2 + half_idx] = __float2half(eluf(acc.z));
            xh[(3 * 216) * 2 + half_idx] = __float2half(eluf(acc.w));
        }
        __syncthreads();

        // ===== B: GRU GEMM via HMMA (warps 0-18, 4 n-tiles each) =====
        if (wid < 19) {
            const int baseT = wid * 4;
            float c[4][4];
#pragma unroll
            for (int tt = 0; tt < 4; tt++)
                c[tt][0] = c[tt][1] = c[tt][2] = c[tt][3] = 0.f;
            const uint2* wb = g_WB_gru + (size_t)baseT * KS_GRU * 32 + lane;
            uint2 P0[4], P1[4];
#pragma unroll
            for (int tt = 0; tt < 4; tt++) {
                P0[tt] = wb[(size_t)tt * KS_GRU * 32 + 0 * 32];
                P1[tt] = wb[(size_t)tt * KS_GRU * 32 + 1 * 32];
            }
            for (int ks = 0; ks < KS_GRU; ks++) {
                int ksn = (ks + 2 < KS_GRU) ? ks + 2 : KS_GRU - 1;
                uint2 Pn[4];
#pragma unroll
                for (int tt = 0; tt < 4; tt++)
                    Pn[tt] = wb[(size_t)tt * KS_GRU * 32 + (size_t)ksn * 32];
                unsigned a0 = 0, a2 = 0;
                if (gr < 4) {
                    int ab = gr * 216 + ks * 8 + tk;
                    a0 = s_xA[ab];
                    a2 = s_xA[ab + 4];
                }
#pragma unroll
                for (int tt = 0; tt < 4; tt++)
                    mma16816(c[tt][0], c[tt][1], c[tt][2], c[tt][3],
                             a0, 0u, a2, 0u, P0[tt].x, P0[tt].y);
#pragma unroll
                for (int tt = 0; tt < 4; tt++) { P0[tt] = P1[tt]; P1[tt] = Pn[tt]; }
            }
            if (gr < 4) {
#pragma unroll
                for (int tt = 0; tt < 4; tt++) {
                    int cbase = (baseT + tt) * 8 + 2 * tk;   // < 608
                    *(float2*)&s_gates[gr * 608 + cbase] = make_float2(c[tt][0], c[tt][1]);
                }
            }
        }
        __syncthreads();

        // ===== B2: gate combine -> deter_new (200 thr, fp32 master) =====
        if (tid < 200) {
            const int u = tid;
            __half* dh = (__half*)s_xA;
            int half_idx = (100 + (u >> 1)) * 2 + (u & 1);
#pragma unroll
            for (int r = 0; r < R; r++) {
                float grv = s_gates[r * 608 + u];
                float gcv = s_gates[r * 608 + 200 + u];
                float guv = s_gates[r * 608 + 400 + u];
                float dold = s_det[r * 200 + u];
                float reset = sigmoidf_(grv);
                float cand  = tanhf(reset * gcv);
                float upd   = sigmoidf_(guv - 1.0f);
                float dn    = upd * cand + (1.f - upd) * dold;
                s_det[r * 200 + u] = dn;
                dh[r * 216 * 2 + half_idx] = __float2half(dn);
                out[(((size_t)(row0 + r)) * NT + t) * OUTC + 180 + u] = dn;
            }
        }
        __syncthreads();

        // ===== C/D: h & ho via HMMA (warps 0-12, 4 n-tiles each) =====
        if (wid < 13) {
            const int baseT = wid * 4;
            float c[4][4];
#pragma unroll
            for (int tt = 0; tt < 4; tt++)
                c[tt][0] = c[tt][1] = c[tt][2] = c[tt][3] = 0.f;
            const uint2* wb = g_WB_io + (size_t)baseT * KS_IO * 32 + lane;
            uint2 P0[4], P1[4];
#pragma unroll
            for (int tt = 0; tt < 4; tt++) {
                P0[tt] = wb[(size_t)tt * KS_IO * 32 + 0 * 32];
                P1[tt] = wb[(size_t)tt * KS_IO * 32 + 1 * 32];
            }
            for (int ks = 0; ks < KS_IO; ks++) {
                int ksn = (ks + 2 < KS_IO) ? ks + 2 : KS_IO - 1;
                uint2 Pn[4];
#pragma unroll
                for (int tt = 0; tt < 4; tt++)
                    Pn[tt] = wb[(size_t)tt * KS_IO * 32 + (size_t)ksn * 32];
                unsigned a0 = 0, a2 = 0;
                if (gr < 4) {
                    int ab = gr * 216 + 100 + ks * 8 + tk;
                    a0 = s_xA[ab];
                    a2 = s_xA[ab + 4];
                }
#pragma unroll
                for (int tt = 0; tt < 4; tt++)
                    mma16816(c[tt][0], c[tt][1], c[tt][2], c[tt][3],
                             a0, 0u, a2, 0u, P0[tt].x, P0[tt].y);
#pragma unroll
                for (int tt = 0; tt < 4; tt++) { P0[tt] = P1[tt]; P1[tt] = Pn[tt]; }
            }
            if (gr < 4) {
#pragma unroll
                for (int tt = 0; tt < 4; tt++) {
                    int tile = baseT + tt;
                    if (tile < 50) {
                        if (tile < 25) {
                            int p = tile * 4 + tk;
                            s_hA[gr * 116 + p] = h2(eluf(c[tt][0]), eluf(c[tt][1]));
                        } else {
                            int tl = tile - 25;
                            int j  = tl * 8 + 2 * tk;
                            int p  = tl * 4 + tk;
                            float o0 = eluf(c[tt][0] + s_po2[j * 4 + gr]);
                            float o1 = eluf(c[tt][1] + s_po2[(j + 1) * 4 + gr]);
                            s_hoA[gr * 116 + p] = h2(o0, o1);
                        }
                    }
                }
            }
        }
        __syncthreads();

        // ===== E/F via HMMA (warps 0-15, 1 tile each) + stage t+1 (warps 16-19) =====
        if (wid < 16) {
            const bool is_e = wid < 8;
            const unsigned* aA = is_e ? s_hA : s_hoA;
            const uint2* wb = g_WB_ef + (size_t)wid * KS_EF * 32 + lane;
            float c0 = 0.f, c1 = 0.f, c2 = 0.f, c3 = 0.f;
            uint2 P0 = wb[0], P1 = wb[32];
            for (int ks = 0; ks < KS_EF; ks++) {
                int ksn = (ks + 2 < KS_EF) ? ks + 2 : KS_EF - 1;
                uint2 Pn = wb[(size_t)ksn * 32];
                unsigned a0 = 0, a2 = 0;
                if (gr < 4) {
                    int ab = gr * 116 + ks * 8 + tk;
                    a0 = aA[ab];
                    a2 = aA[ab + 4];
                }
                mma16816(c0, c1, c2, c3, a0, 0u, a2, 0u, P0.x, P0.y);
                P0 = P1; P1 = Pn;
            }
            if (gr < 4) {
                int cc = (wid & 7) * 8 + 2 * tk;
                int off = is_e ? 0 : 64;
                *(float2*)&s_stat[gr * 128 + off + cc] = make_float2(c0, c1);
            }
        } else if (t + 1 < NT) {
            for (int i = tid - 512; i < 800; i += 128) {
                int j = i >> 2, r = i & 3;
                size_t base = ((size_t)(row0 + r) * NT + (t + 1)) * NH + j;
                s_pi [i] = g_pre_inp[base];
                s_po2[i] = g_pre_obs[base];
            }
        }
        __syncthreads();

        // ===== finalize: sample, write, carry (stats include biases) =====
        if (tid < NS) {                       // prior (ims)
            const int u = tid;
#pragma unroll
            for (int r = 0; r < R; r++) {
                float m  = s_stat[r * 128 + u];
                float sd = softplusf_(s_stat[r * 128 + 30 + u]) + 0.1f;
                size_t bt = ((size_t)(row0 + r)) * NT + t;
                float nz = noise_prior[bt * NS + u];
                size_t ob = bt * OUTC;
                out[ob + 120 + u] = m;
                out[ob + 150 + u] = sd;
                out[ob +  90 + u] = m + sd * nz;
            }
        } else if (tid >= 32 && tid < 32 + NS) {  // posterior (obs)
            const int u = tid - 32;
#pragma unroll
            for (int r = 0; r < R; r++) {
                float m  = s_stat[r * 128 + 64 + u];
                float sd = softplusf_(s_stat[r * 128 + 94 + u]) + 0.1f;
                size_t bt = ((size_t)(row0 + r)) * NT + t;
                float nz = noise_post[bt * NS + u];
                float st = m + sd * nz;
                size_t ob = bt * OUTC;
                out[ob + 30 + u] = m;
                out[ob + 60 + u] = sd;
                out[ob +  0 + u] = st;
                s_stoch[r * 32 + u] = st;
            }
        }
        __syncthreads();
    }
}

// =====================================================================
extern "C" void kernel_launch(void* const* d_in, const int* in_sizes, int n_in,
                              void* d_out, int out_size) {
    const float* embed       = (const float*)d_in[0];
    const float* action      = (const float*)d_in[1];
    const float* noise_prior = (const float*)d_in[2];
    const float* noise_post  = (const float*)d_in[3];
    const float* inp_W       = (const float*)d_in[4];
    const float* inp_b       = (const float*)d_in[5];
    const float* gru_W       = (const float*)d_in[6];
    const float* gru_b       = (const float*)d_in[7];
    const float* img_out_W   = (const float*)d_in[8];
    const float* img_out_b   = (const float*)d_in[9];
    const float* ims_W       = (const float*)d_in[10];
    const float* ims_b       = (const float*)d_in[11];
    const float* obs_out_W   = (const float*)d_in[12];
    const float* obs_out_b   = (const float*)d_in[13];
    const float* obs_W       = (const float*)d_in[14];
    const float* obs_b       = (const float*)d_in[15];
    float* out = (float*)d_out;

    precompute_kernel<<<(NB * NT) / PRE_ROWS, 224>>>(
        embed, action, obs_out_W, obs_out_b, inp_W, inp_b,
        gru_W, gru_b, img_out_W, img_out_b, ims_W, ims_b, obs_W, obs_b);
    scan_kernel<<<NCTA, 640>>>(noise_prior, noise_post, inp_W, out);
}

// round 15
// speedup vs baseline: 1.7135x; 1.1879x over previous
#include <cuda_runtime.h>
#include <cuda_fp16.h>
#include <math.h>

#define NB 512
#define NT 64
#define NS 30
#define ND 200
#define NH 200
#define NA 12
#define NE 1024
#define OUTC 380
#define R 4
#define NCTA (NB / R)   // 128

// MMA tilings (m16n8k16)
#define KS_GRU 26
#define NTI_GRU 76
#define KS_IO  14
#define NTI_IO 50
#define KS_EF  14
#define NTI_EF 16
#define KS_PRE 64       // K = 1024
#define NTI_PRE 25      // N = 200

// ---------------- device-global scratch (allocation-free rule) ----------------
__device__ __align__(16) uint2 g_WB_gru[NTI_GRU * KS_GRU * 32];
__device__ __align__(16) uint2 g_WB_io [NTI_IO  * KS_IO  * 32];
__device__ __align__(16) uint2 g_WB_ef [NTI_EF  * KS_EF  * 32];
__device__ __align__(16) uint2 g_WB_pre[NTI_PRE * KS_PRE * 32];
__device__ float g_pre_inp[NB * NT * NH];
__device__ float g_pre_obs[NB * NT * NH];

typedef unsigned long long ull;

// ---------------- helpers ----------------
__device__ __forceinline__ unsigned h2(float a, float b) {
    __half2 h = __floats2half2_rn(a, b);
    return *(unsigned*)&h;
}
__device__ __forceinline__ void mma16816(float& c0, float& c1, float& c2, float& c3,
                                         unsigned a0, unsigned a1, unsigned a2, unsigned a3,
                                         unsigned b0, unsigned b1) {
    asm volatile(
        "mma.sync.aligned.m16n8k16.row.col.f32.f16.f16.f32 "
        "{%0,%1,%2,%3},{%4,%5,%6,%7},{%8,%9},{%0,%1,%2,%3};"
        : "+f"(c0), "+f"(c1), "+f"(c2), "+f"(c3)
        : "r"(a0), "r"(a1), "r"(a2), "r"(a3), "r"(b0), "r"(b1));
}
__device__ __forceinline__ float eluf(float z)      { return z > 0.f ? z : expm1f(z); }
__device__ __forceinline__ float sigmoidf_(float z) { return 1.f / (1.f + expf(-z)); }
__device__ __forceinline__ float softplusf_(float z){ return fmaxf(z, 0.f) + log1pf(expf(-fabsf(z))); }

// =====================================================================
// Kernel 0: pack ALL weights into HMMA B-fragment lane order
// =====================================================================
__global__ void convert_kernel(const float* __restrict__ gru_W,
                               const float* __restrict__ gru_b,
                               const float* __restrict__ img_W,
                               const float* __restrict__ img_out_b,
                               const float* __restrict__ ims_W,
                               const float* __restrict__ ims_b,
                               const float* __restrict__ obs_W,
                               const float* __restrict__ obs_b,
                               const float* __restrict__ obs_out_W)
{
    int gt = blockIdx.x * blockDim.x + threadIdx.x;
    // GRU: K rows = [x(200); deter(200); bias; zeros]
    if (gt < NTI_GRU * KS_GRU * 32) {
        int lane = gt & 31;
        int ks   = (gt >> 5) % KS_GRU;
        int tile = (gt >> 5) / KS_GRU;
        int tk = lane & 3, gc = lane >> 2;
        int n = tile * 8 + gc;
        int k0 = ks * 16 + 2 * tk;
        float v[4];
#pragma unroll
        for (int e = 0; e < 4; e++) {
            int k = k0 + (e >= 2 ? 8 : 0) + (e & 1);
            float w = 0.f;
            if (n < 600) {
                if (k < 400) w = gru_W[k * 600 + n];
                else if (k == 400) w = gru_b[n];
            }
            v[e] = w;
        }
        g_WB_gru[gt] = make_uint2(h2(v[0], v[1]), h2(v[2], v[3]));
    }
    // IO: K rows = [deter(200); bias(img only); zeros]; tiles 0-24 img, 25-49 obs
    if (gt < NTI_IO * KS_IO * 32) {
        int lane = gt & 31;
        int ks   = (gt >> 5) % KS_IO;
        int tile = (gt >> 5) / KS_IO;
        int tk = lane & 3, gc = lane >> 2;
        bool is_img = tile < 25;
        int n = (is_img ? tile : tile - 25) * 8 + gc;
        int k0 = ks * 16 + 2 * tk;
        float v[4];
#pragma unroll
        for (int e = 0; e < 4; e++) {
            int k = k0 + (e >= 2 ? 8 : 0) + (e & 1);
            float w = 0.f;
            if (k < 200) w = (is_img ? img_W : obs_out_W)[k * 200 + n];
            else if (k == 200 && is_img) w = img_out_b[n];
            v[e] = w;
        }
        g_WB_io[gt] = make_uint2(h2(v[0], v[1]), h2(v[2], v[3]));
    }
    // EF: K rows = [h/ho(200); bias; zeros]; tiles 0-7 ims(E), 8-15 obs(F)
    if (gt < NTI_EF * KS_EF * 32) {
        int lane = gt & 31;
        int ks   = (gt >> 5) % KS_EF;
        int tile = (gt >> 5) / KS_EF;
        int tk = lane & 3, gc = lane >> 2;
        bool is_e = tile < 8;
        int n = (is_e ? tile : tile - 8) * 8 + gc;
        int k0 = ks * 16 + 2 * tk;
        float v[4];
#pragma unroll
        for (int e = 0; e < 4; e++) {
            int k = k0 + (e >= 2 ? 8 : 0) + (e & 1);
            float w = 0.f;
            if (n < 60) {
                if (k < 200) w = (is_e ? ims_W : obs_W)[k * 60 + n];
                else if (k == 200) w = (is_e ? ims_b : obs_b)[n];
            }
            v[e] = w;
        }
        g_WB_ef[gt] = make_uint2(h2(v[0], v[1]), h2(v[2], v[3]));
    }
    // PRE: obs_out_W rows 200..1223 (embed part), K = 1024, N = 200
    if (gt < NTI_PRE * KS_PRE * 32) {
        int lane = gt & 31;
        int ks   = (gt >> 5) % KS_PRE;
        int nt   = (gt >> 5) / KS_PRE;
        int tk = lane & 3, gc = lane >> 2;
        int n = nt * 8 + gc;              // < 200
        int k0 = ks * 16 + 2 * tk;
        const float* W2 = obs_out_W + (size_t)ND * NH;
        float v[4];
#pragma unroll
        for (int e = 0; e < 4; e++) {
            int k = k0 + (e >= 2 ? 8 : 0) + (e & 1);   // < 1024 always
            v[e] = W2[(size_t)k * NH + n];
        }
        g_WB_pre[gt] = make_uint2(h2(v[0], v[1]), h2(v[2], v[3]));
    }
}

// =====================================================================
// Kernel 1: precompute via HMMA.
// Grid 512 CTAs x 64 bt-rows; 8 warps = 4 m-tiles x 2 n-groups.
// pre_obs = embed @ obs_out_W[200:] + obs_out_b  (fp16 MMA, fp32 accum)
// pre_inp = action @ inp_W[30:] + inp_b          (SIMT tail)
// =====================================================================
__global__ void __launch_bounds__(256) precompute_kernel(
    const float* __restrict__ embed,
    const float* __restrict__ action,
    const float* __restrict__ obs_out_b,
    const float* __restrict__ inp_W,
    const float* __restrict__ inp_b)
{
    const int tid  = threadIdx.x;
    const int wid  = tid >> 5;
    const int lane = tid & 31;
    const int tk   = lane & 3;
    const int gr   = lane >> 2;
    const int mt   = wid & 3;            // m-tile within CTA
    const int ng   = wid >> 2;           // n-group: 0 -> tiles 0..12, 1 -> 13..24
    const int nt0  = ng ? 13 : 0;
    const int nti  = ng ? 12 : 13;

    const int bt0 = blockIdx.x * 64 + mt * 16;   // this warp's 16 rows

    float acc[13][4];
#pragma unroll
    for (int i = 0; i < 13; i++)
        acc[i][0] = acc[i][1] = acc[i][2] = acc[i][3] = 0.f;

    const float2* e0 = (const float2*)(embed + (size_t)(bt0 + gr) * NE);
    const float2* e1 = (const float2*)(embed + (size_t)(bt0 + gr + 8) * NE);
    const uint2* bp = g_WB_pre + (size_t)nt0 * KS_PRE * 32 + lane;

    for (int ks = 0; ks < KS_PRE; ks++) {
        float2 f0 = e0[ks * 8 + tk];
        float2 f1 = e1[ks * 8 + tk];
        float2 f2 = e0[ks * 8 + tk + 4];
        float2 f3 = e1[ks * 8 + tk + 4];
        unsigned a0 = h2(f0.x, f0.y);
        unsigned a1 = h2(f1.x, f1.y);
        unsigned a2 = h2(f2.x, f2.y);
        unsigned a3 = h2(f3.x, f3.y);
        const uint2* bk = bp + (size_t)ks * 32;
#pragma unroll 13
        for (int i = 0; i < 13; i++) {
            if (i < nti) {
                uint2 B = bk[(size_t)i * KS_PRE * 32];
                mma16816(acc[i][0], acc[i][1], acc[i][2], acc[i][3],
                         a0, a1, a2, a3, B.x, B.y);
            }
        }
    }

    // epilogue: add bias, store fp32
#pragma unroll 13
    for (int i = 0; i < 13; i++) {
        if (i < nti) {
            int n0 = (nt0 + i) * 8 + 2 * tk;
            float b0 = obs_out_b[n0], b1 = obs_out_b[n0 + 1];
            *(float2*)&g_pre_obs[(size_t)(bt0 + gr) * NH + n0] =
                make_float2(acc[i][0] + b0, acc[i][1] + b1);
            *(float2*)&g_pre_obs[(size_t)(bt0 + gr + 8) * NH + n0] =
                make_float2(acc[i][2] + b0, acc[i][3] + b1);
        }
    }

    // ---- pre_inp (SIMT, K=12) ----
    const int base = blockIdx.x * 64;
    for (int idx = tid; idx < 64 * NH; idx += 256) {
        int rr = idx / NH, j = idx % NH;
        int bt = base + rr;
        float a = inp_b[j];
#pragma unroll
        for (int k = 0; k < NA; k++)
            a = fmaf(action[(size_t)bt * NA + k], inp_W[(NS + k) * NH + j], a);
        g_pre_inp[(size_t)bt * NH + j] = a;
    }
}

// =====================================================================
// Kernel 2: scan via warp-level HMMA (unchanged from R14).
// =====================================================================
__global__ void __launch_bounds__(640) scan_kernel(
    const float* __restrict__ noise_prior,
    const float* __restrict__ noise_post,
    const float* __restrict__ inp_W,
    float* __restrict__ out)
{
    __shared__ __align__(16) unsigned s_xA [4 * 216];
    __shared__ __align__(16) unsigned s_hA [4 * 116];
    __shared__ __align__(16) unsigned s_hoA[4 * 116];
    __shared__ __align__(16) float s_gates[4 * 608];
    __shared__ __align__(16) float s_det  [4 * 200];
    __shared__ __align__(16) float s_stat [4 * 128];
    __shared__ __align__(16) float s_pi [800];
    __shared__ __align__(16) float s_po2[800];
    __shared__ __align__(16) float s_stoch[128];

    const int tid  = threadIdx.x;
    const int wid  = tid >> 5;
    const int lane = tid & 31;
    const int tk   = lane & 3;
    const int gr   = lane >> 2;
    const int row0 = blockIdx.x * R;

    for (int i = tid; i < 4 * 216; i += 640) { int p = i % 216; s_xA[i] = (p == 200) ? 0x00003C00u : 0u; }
    for (int i = tid; i < 4 * 116; i += 640) { int p = i % 116; unsigned v = (p == 100) ? 0x00003C00u : 0u; s_hA[i] = v; s_hoA[i] = v; }
    for (int i = tid; i < 800; i += 640) s_det[i] = 0.f;
    for (int i = tid; i < 128; i += 640) s_stoch[i] = 0.f;
    for (int i = tid; i < 800; i += 640) {
        int j = i >> 2, r = i & 3;
        size_t base = ((size_t)(row0 + r) * NT + 0) * NH + j;
        s_pi [i] = g_pre_inp[base];
        s_po2[i] = g_pre_obs[base];
    }
    __syncthreads();

    for (int t = 0; t < NT; t++) {
        // ===== A: x = elu(stoch @ inp_W[:30] + pre_inp) (200 thr, fp32) =====
        if (tid < 200) {
            const int j = tid;
            float4 acc = *(const float4*)&s_pi[j * 4];
#pragma unroll
            for (int k = 0; k < NS; k++) {
                float w = inp_W[k * NH + j];
                acc.x = fmaf(w, s_stoch[0 * 32 + k], acc.x);
                acc.y = fmaf(w, s_stoch[1 * 32 + k], acc.y);
                acc.z = fmaf(w, s_stoch[2 * 32 + k], acc.z);
                acc.w = fmaf(w, s_stoch[3 * 32 + k], acc.w);
            }
            __half* xh = (__half*)s_xA;
            int half_idx = (j >> 1) * 2 + (j & 1);
            xh[(0 * 216) * 2 + half_idx] = __float2half(eluf(acc.x));
            xh[(1 * 216) * 2 + half_idx] = __float2half(eluf(acc.y));
            xh[(2 * 216) * 2 + half_idx] = __float2half(eluf(acc.z));
            xh[(3 * 216) * 2 + half_idx] = __float2half(eluf(acc.w));
        }
        __syncthreads();

        // ===== B: GRU GEMM via HMMA (warps 0-18, 4 n-tiles each) =====
        if (wid < 19) {
            const int baseT = wid * 4;
            float c[4][4];
#pragma unroll
            for (int tt = 0; tt < 4; tt++)
                c[tt][0] = c[tt][1] = c[tt][2] = c[tt][3] = 0.f;
            const uint2* wb = g_WB_gru + (size_t)baseT * KS_GRU * 32 + lane;
            uint2 P0[4], P1[4];
#pragma unroll
            for (int tt = 0; tt < 4; tt++) {
                P0[tt] = wb[(size_t)tt * KS_GRU * 32 + 0 * 32];
                P1[tt] = wb[(size_t)tt * KS_GRU * 32 + 1 * 32];
            }
            for (int ks = 0; ks < KS_GRU; ks++) {
                int ksn = (ks + 2 < KS_GRU) ? ks + 2 : KS_GRU - 1;
                uint2 Pn[4];
#pragma unroll
                for (int tt = 0; tt < 4; tt++)
                    Pn[tt] = wb[(size_t)tt * KS_GRU * 32 + (size_t)ksn * 32];
                unsigned a0 = 0, a2 = 0;
                if (gr < 4) {
                    int ab = gr * 216 + ks * 8 + tk;
                    a0 = s_xA[ab];
                    a2 = s_xA[ab + 4];
                }
#pragma unroll
                for (int tt = 0; tt < 4; tt++)
                    mma16816(c[tt][0], c[tt][1], c[tt][2], c[tt][3],
                             a0, 0u, a2, 0u, P0[tt].x, P0[tt].y);
#pragma unroll
                for (int tt = 0; tt < 4; tt++) { P0[tt] = P1[tt]; P1[tt] = Pn[tt]; }
            }
            if (gr < 4) {
#pragma unroll
                for (int tt = 0; tt < 4; tt++) {
                    int cbase = (baseT + tt) * 8 + 2 * tk;
                    *(float2*)&s_gates[gr * 608 + cbase] = make_float2(c[tt][0], c[tt][1]);
                }
            }
        }
        __syncthreads();

        // ===== B2: gate combine -> deter_new (200 thr, fp32 master) =====
        if (tid < 200) {
            const int u = tid;
            __half* dh = (__half*)s_xA;
            int half_idx = (100 + (u >> 1)) * 2 + (u & 1);
#pragma unroll
            for (int r = 0; r < R; r++) {
                float grv = s_gates[r * 608 + u];
                float gcv = s_gates[r * 608 + 200 + u];
                float guv = s_gates[r * 608 + 400 + u];
                float dold = s_det[r * 200 + u];
                float reset = sigmoidf_(grv);
                float cand  = tanhf(reset * gcv);
                float upd   = sigmoidf_(guv - 1.0f);
                float dn    = upd * cand + (1.f - upd) * dold;
                s_det[r * 200 + u] = dn;
                dh[r * 216 * 2 + half_idx] = __float2half(dn);
                out[(((size_t)(row0 + r)) * NT + t) * OUTC + 180 + u] = dn;
            }
        }
        __syncthreads();

        // ===== C/D: h & ho via HMMA (warps 0-12, 4 n-tiles each) =====
        if (wid < 13) {
            const int baseT = wid * 4;
            float c[4][4];
#pragma unroll
            for (int tt = 0; tt < 4; tt++)
                c[tt][0] = c[tt][1] = c[tt][2] = c[tt][3] = 0.f;
            const uint2* wb = g_WB_io + (size_t)baseT * KS_IO * 32 + lane;
            uint2 P0[4], P1[4];
#pragma unroll
            for (int tt = 0; tt < 4; tt++) {
                P0[tt] = wb[(size_t)tt * KS_IO * 32 + 0 * 32];
                P1[tt] = wb[(size_t)tt * KS_IO * 32 + 1 * 32];
            }
            for (int ks = 0; ks < KS_IO; ks++) {
                int ksn = (ks + 2 < KS_IO) ? ks + 2 : KS_IO - 1;
                uint2 Pn[4];
#pragma unroll
                for (int tt = 0; tt < 4; tt++)
                    Pn[tt] = wb[(size_t)tt * KS_IO * 32 + (size_t)ksn * 32];
                unsigned a0 = 0, a2 = 0;
                if (gr < 4) {
                    int ab = gr * 216 + 100 + ks * 8 + tk;
                    a0 = s_xA[ab];
                    a2 = s_xA[ab + 4];
                }
#pragma unroll
                for (int tt = 0; tt < 4; tt++)
                    mma16816(c[tt][0], c[tt][1], c[tt][2], c[tt][3],
                             a0, 0u, a2, 0u, P0[tt].x, P0[tt].y);
#pragma unroll
                for (int tt = 0; tt < 4; tt++) { P0[tt] = P1[tt]; P1[tt] = Pn[tt]; }
            }
            if (gr < 4) {
#pragma unroll
                for (int tt = 0; tt < 4; tt++) {
                    int tile = baseT + tt;
                    if (tile < 50) {
                        if (tile < 25) {
                            int p = tile * 4 + tk;
                            s_hA[gr * 116 + p] = h2(eluf(c[tt][0]), eluf(c[tt][1]));
                        } else {
                            int tl = tile - 25;
                            int j  = tl * 8 + 2 * tk;
                            int p  = tl * 4 + tk;
                            float o0 = eluf(c[tt][0] + s_po2[j * 4 + gr]);
                            float o1 = eluf(c[tt][1] + s_po2[(j + 1) * 4 + gr]);
                            s_hoA[gr * 116 + p] = h2(o0, o1);
                        }
                    }
                }
            }
        }
        __syncthreads();

        // ===== E/F via HMMA (warps 0-15) + stage t+1 (warps 16-19) =====
        if (wid < 16) {
            const bool is_e = wid < 8;
            const unsigned* aA = is_e ? s_hA : s_hoA;
            const uint2* wb = g_WB_ef + (size_t)wid * KS_EF * 32 + lane;
            float c0 = 0.f, c1 = 0.f, c2 = 0.f, c3 = 0.f;
            uint2 P0 = wb[0], P1 = wb[32];
            for (int ks = 0; ks < KS_EF; ks++) {
                int ksn = (ks + 2 < KS_EF) ? ks + 2 : KS_EF - 1;
                uint2 Pn = wb[(size_t)ksn * 32];
                unsigned a0 = 0, a2 = 0;
                if (gr < 4) {
                    int ab = gr * 116 + ks * 8 + tk;
                    a0 = aA[ab];
                    a2 = aA[ab + 4];
                }
                mma16816(c0, c1, c2, c3, a0, 0u, a2, 0u, P0.x, P0.y);
                P0 = P1; P1 = Pn;
            }
            if (gr < 4) {
                int cc = (wid & 7) * 8 + 2 * tk;
                int off = is_e ? 0 : 64;
                *(float2*)&s_stat[gr * 128 + off + cc] = make_float2(c0, c1);
            }
        } else if (t + 1 < NT) {
            for (int i = tid - 512; i < 800; i += 128) {
                int j = i >> 2, r = i & 3;
                size_t base = ((size_t)(row0 + r) * NT + (t + 1)) * NH + j;
                s_pi [i] = g_pre_inp[base];
                s_po2[i] = g_pre_obs[base];
            }
        }
        __syncthreads();

        // ===== finalize: sample, write, carry =====
        if (tid < NS) {
            const int u = tid;
#pragma unroll
            for (int r = 0; r < R; r++) {
                float m  = s_stat[r * 128 + u];
                float sd = softplusf_(s_stat[r * 128 + 30 + u]) + 0.1f;
                size_t bt = ((size_t)(row0 + r)) * NT + t;
                float nz = noise_prior[bt * NS + u];
                size_t ob = bt * OUTC;
                out[ob + 120 + u] = m;
                out[ob + 150 + u] = sd;
                out[ob +  90 + u] = m + sd * nz;
            }
        } else if (tid >= 32 && tid < 32 + NS) {
            const int u = tid - 32;
#pragma unroll
            for (int r = 0; r < R; r++) {
                float m  = s_stat[r * 128 + 64 + u];
                float sd = softplusf_(s_stat[r * 128 + 94 + u]) + 0.1f;
                size_t bt = ((size_t)(row0 + r)) * NT + t;
                float nz = noise_post[bt * NS + u];
                float st = m + sd * nz;
                size_t ob = bt * OUTC;
                out[ob + 30 + u] = m;
                out[ob + 60 + u] = sd;
                out[ob +  0 + u] = st;
                s_stoch[r * 32 + u] = st;
            }
        }
        __syncthreads();
    }
}

// =====================================================================
extern "C" void kernel_launch(void* const* d_in, const int* in_sizes, int n_in,
                              void* d_out, int out_size) {
    const float* embed       = (const float*)d_in[0];
    const float* action      = (const float*)d_in[1];
    const float* noise_prior = (const float*)d_in[2];
    const float* noise_post  = (const float*)d_in[3];
    const float* inp_W       = (const float*)d_in[4];
    const float* inp_b       = (const float*)d_in[5];
    const float* gru_W       = (const float*)d_in[6];
    const float* gru_b       = (const float*)d_in[7];
    const float* img_out_W   = (const float*)d_in[8];
    const float* img_out_b   = (const float*)d_in[9];
    const float* ims_W       = (const float*)d_in[10];
    const float* ims_b       = (const float*)d_in[11];
    const float* obs_out_W   = (const float*)d_in[12];
    const float* obs_out_b   = (const float*)d_in[13];
    const float* obs_W       = (const float*)d_in[14];
    const float* obs_b       = (const float*)d_in[15];
    float* out = (float*)d_out;

    convert_kernel<<<(NTI_GRU * KS_GRU * 32 + 255) / 256, 256>>>(
        gru_W, gru_b, img_out_W, img_out_b, ims_W, ims_b, obs_W, obs_b, obs_out_W);
    precompute_kernel<<<(NB * NT) / 64, 256>>>(embed, action, obs_out_b, inp_W, inp_b);
    scan_kernel<<<NCTA, 640>>>(noise_prior, noise_post, inp_W, out);
}